// round 2
// baseline (speedup 1.0000x reference)
#include <cuda_runtime.h>
#include <math.h>
#include <stdint.h>

#define N_NODES 100000
#define N_EDGES 1000000
#define DIM     128
#define NH      4
#define NJ      8
#define NK      1000
#define NC      40
#define TOPK    8000            // NJ*NK per head
#define NBINS   65536
#define CAP     16384
#define NNZ_CAP (1<<22)
#define NG      32              // NJ*NH

// ---------------- static device scratch (no runtime allocation) ----------------
__device__ int                 d_deg[N_NODES];
__device__ float               d_p[N_NODES * NH];
__device__ float               d_scores[N_NODES * NH];
__device__ unsigned            d_hist[NH * NBINS];
__device__ int                 d_B[NH];
__device__ int                 d_ccount[NH];
__device__ unsigned long long  d_cbuf[NH * CAP];
__device__ int                 d_sidx[NH * TOPK];
__device__ float               d_vals[NH * TOPK];
__device__ int                 d_locmap[N_NODES * NH];   // [n][h], 0 = absent, else rank+1
__device__ int                 d_nnzcnt;
__device__ uint2               d_nnz[NNZ_CAP];
__device__ float               d_msg[NG * NK * DIM];     // [g][ku][d]
__device__ float               d_pooled[NJ * DIM];

// ---------------- helpers ----------------
__device__ __forceinline__ unsigned flip_key(float f) {
    unsigned u = __float_as_uint(f);
    return (u >> 31) ? ~u : (u | 0x80000000u);
}

// ---------------- kernels ----------------

// degree count (deg = incoming-edge count; +1 applied at use sites)
__global__ void k_deg(const int* __restrict__ ei) {
    int e = blockIdx.x * blockDim.x + threadIdx.x;
    if (e < N_EDGES) atomicAdd(&d_deg[__ldg(&ei[N_EDGES + e])], 1);
}

// p = x @ w_rank  (warp per node)
__global__ void k_p(const float* __restrict__ x, const float* __restrict__ wr) {
    int warp = (blockIdx.x * blockDim.x + threadIdx.x) >> 5;
    int lane = threadIdx.x & 31;
    if (warp >= N_NODES) return;
    const float* xr = x + (size_t)warp * DIM;
    float a0 = 0, a1 = 0, a2 = 0, a3 = 0;
    #pragma unroll
    for (int c0 = 0; c0 < DIM; c0 += 32) {
        int c = c0 + lane;
        float xv = __ldg(&xr[c]);
        float4 w4 = __ldg(reinterpret_cast<const float4*>(&wr[c * NH]));
        a0 += xv * w4.x; a1 += xv * w4.y; a2 += xv * w4.z; a3 += xv * w4.w;
    }
    #pragma unroll
    for (int o = 16; o; o >>= 1) {
        a0 += __shfl_down_sync(0xFFFFFFFFu, a0, o);
        a1 += __shfl_down_sync(0xFFFFFFFFu, a1, o);
        a2 += __shfl_down_sync(0xFFFFFFFFu, a2, o);
        a3 += __shfl_down_sync(0xFFFFFFFFu, a3, o);
    }
    if (lane == 0) {
        float4* dst = reinterpret_cast<float4*>(&d_p[warp * NH]);
        *dst = make_float4(a0, a1, a2, a3);
    }
}

// scores[n,h] = p[n,h] / deg[n]
__global__ void k_scores_init() {
    int n = blockIdx.x * blockDim.x + threadIdx.x;
    if (n >= N_NODES) return;
    float inv = 1.0f / ((float)d_deg[n] + 1.0f);
    float4 p4 = *reinterpret_cast<const float4*>(&d_p[n * NH]);
    *reinterpret_cast<float4*>(&d_scores[n * NH]) =
        make_float4(p4.x * inv, p4.y * inv, p4.z * inv, p4.w * inv);
}

// scores[v,h] += rsqrt(deg[u]*deg[v]) * p[u,h]
__global__ void k_scores_edges(const int* __restrict__ ei) {
    int e = blockIdx.x * blockDim.x + threadIdx.x;
    if (e >= N_EDGES) return;
    int u = __ldg(&ei[e]), v = __ldg(&ei[N_EDGES + e]);
    float du = (float)__ldg(&d_deg[u]) + 1.0f;
    float dv = (float)__ldg(&d_deg[v]) + 1.0f;
    float nrm = rsqrtf(du * dv);
    float4 p4 = __ldg(reinterpret_cast<const float4*>(&d_p[u * NH]));
    atomicAdd(&d_scores[v * NH + 0], nrm * p4.x);
    atomicAdd(&d_scores[v * NH + 1], nrm * p4.y);
    atomicAdd(&d_scores[v * NH + 2], nrm * p4.z);
    atomicAdd(&d_scores[v * NH + 3], nrm * p4.w);
}

// per-head 16-bit radix histogram of flipped score keys
__global__ void k_hist() {
    int n = blockIdx.x * blockDim.x + threadIdx.x;
    if (n >= N_NODES) return;
    float4 s4 = *reinterpret_cast<const float4*>(&d_scores[n * NH]);
    atomicAdd(&d_hist[0 * NBINS + (flip_key(s4.x) >> 16)], 1u);
    atomicAdd(&d_hist[1 * NBINS + (flip_key(s4.y) >> 16)], 1u);
    atomicAdd(&d_hist[2 * NBINS + (flip_key(s4.z) >> 16)], 1u);
    atomicAdd(&d_hist[3 * NBINS + (flip_key(s4.w) >> 16)], 1u);
}

// find threshold bin B[h]: count(bins > B) < TOPK <= count(bins >= B)
__global__ void k_scan() {
    __shared__ unsigned csum[1024];
    int h = blockIdx.x, t = threadIdx.x;
    unsigned s = 0;
    for (int b = 0; b < 64; b++) s += d_hist[h * NBINS + t * 64 + b];
    csum[t] = s;
    __syncthreads();
    if (t == 0) {
        unsigned tot = 0;
        int tc = 1023;
        for (; tc >= 0; tc--) {
            if (tot + csum[tc] >= TOPK) break;
            tot += csum[tc];
        }
        int bfound = tc * 64;
        for (int b = 63; b >= 0; b--) {
            unsigned hv = d_hist[h * NBINS + tc * 64 + b];
            if (tot + hv >= TOPK) { bfound = tc * 64 + b; break; }
            tot += hv;
        }
        d_B[h] = bfound;
    }
}

// compact candidates (bin >= B) as 64-bit keys (value<<32 | ~idx)
__global__ void k_compact() {
    int n = blockIdx.x * blockDim.x + threadIdx.x;
    if (n >= N_NODES) return;
    float4 s4 = *reinterpret_cast<const float4*>(&d_scores[n * NH]);
    float sv[4] = {s4.x, s4.y, s4.z, s4.w};
    #pragma unroll
    for (int h = 0; h < NH; h++) {
        unsigned key = flip_key(sv[h]);
        if ((int)(key >> 16) >= d_B[h]) {
            int pos = atomicAdd(&d_ccount[h], 1);
            if (pos < CAP)
                d_cbuf[h * CAP + pos] =
                    ((unsigned long long)key << 32) | (unsigned)(~(unsigned)n);
        }
    }
}

// one block per head: bitonic sort candidates, emit top-8000 sorted (desc), fill locmap
__global__ void k_sort() {
    extern __shared__ unsigned long long s[];
    int h = blockIdx.x, t = threadIdx.x;
    int cnt = min(d_ccount[h], CAP);
    int M = (cnt <= 8192) ? 8192 : 16384;
    for (int i = t; i < M; i += blockDim.x)
        s[i] = (i < cnt) ? ~d_cbuf[h * CAP + i] : 0xFFFFFFFFFFFFFFFFull;
    __syncthreads();
    for (int k = 2; k <= M; k <<= 1) {
        for (int j = k >> 1; j > 0; j >>= 1) {
            for (int i = t; i < M; i += blockDim.x) {
                int ixj = i ^ j;
                if (ixj > i) {
                    unsigned long long a = s[i], b = s[ixj];
                    bool up = ((i & k) == 0);
                    if ((a > b) == up) { s[i] = b; s[ixj] = a; }
                }
            }
            __syncthreads();
        }
    }
    for (int r = t; r < TOPK; r += blockDim.x) {
        unsigned long long key = ~s[r];
        unsigned key32 = (unsigned)(key >> 32);
        int n = (int)(~(unsigned)key);
        float f = __uint_as_float((key32 & 0x80000000u) ? (key32 & 0x7FFFFFFFu)
                                                        : ~key32);
        d_sidx[h * TOPK + r] = n;
        d_vals[h * TOPK + r] = f;
        d_locmap[n * NH + h] = r + 1;
    }
}

// edge pass: emit sparse adj triples (g, ku, kv, w)
__global__ void k_nnz(const int* __restrict__ ei, const float* __restrict__ ea) {
    int e = blockIdx.x * blockDim.x + threadIdx.x;
    if (e >= N_EDGES) return;
    int u = __ldg(&ei[e]), v = __ldg(&ei[N_EDGES + e]);
    int4 lu4 = __ldg(reinterpret_cast<const int4*>(&d_locmap[u * NH]));
    int4 lv4 = __ldg(reinterpret_cast<const int4*>(&d_locmap[v * NH]));
    int lus[4] = {lu4.x, lu4.y, lu4.z, lu4.w};
    int lvs[4] = {lv4.x, lv4.y, lv4.z, lv4.w};
    #pragma unroll
    for (int h = 0; h < NH; h++) {
        int lu = lus[h], lv = lvs[h];
        if (lu == 0 || lv == 0) continue;
        int pu = lu - 1, pv = lv - 1;
        int jju = pu / NK;
        if (jju != pv / NK) continue;
        float w = __ldg(&ea[e]);
        int g = jju * NH + h;
        int ku = pu - jju * NK;
        int kv = pv - jju * NK;
        int pos = atomicAdd(&d_nnzcnt, 1);
        if (pos < NNZ_CAP)
            d_nnz[pos] = make_uint2(((unsigned)g << 20) | ((unsigned)ku << 10) | (unsigned)kv,
                                    __float_as_uint(w));
    }
}

// sparse msg: for each triple, msg[g,ku,:] += w * (x[node(g,kv)] @ W1)
__global__ void k_msg(const float* __restrict__ x, const float* __restrict__ W1) {
    __shared__ float xs[DIM];
    int cnt = min(d_nnzcnt, NNZ_CAP);
    int t = threadIdx.x;
    for (int e = blockIdx.x; e < cnt; e += gridDim.x) {
        uint2 en = d_nnz[e];
        int packed = (int)en.x;
        float w = __uint_as_float(en.y);
        int g = packed >> 20, ku = (packed >> 10) & 1023, kv = packed & 1023;
        int hh = g & 3, jj = g >> 2;
        int node = d_sidx[hh * TOPK + jj * NK + kv];
        __syncthreads();
        xs[t] = __ldg(&x[(size_t)node * DIM + t]);
        __syncthreads();
        float acc = 0.0f;
        #pragma unroll 8
        for (int c = 0; c < DIM; c++) acc += xs[c] * __ldg(&W1[c * DIM + t]);
        atomicAdd(&d_msg[((size_t)(g * NK + ku)) * DIM + t], w * acc);
    }
}

// pooled[jj,d] += relu(msg) * sigmoid(perm) over (h,ku)
__global__ void k_pooled() {
    int jj = blockIdx.x >> 5;
    int sl = blockIdx.x & 31;
    int t = threadIdx.x;
    float acc = 0.0f;
    int hk0 = sl * 125;
    for (int hk = hk0; hk < hk0 + 125; hk++) {
        float m = d_msg[((size_t)(jj * 4000 + hk)) * DIM + t];
        if (m > 0.0f) {
            int h = hk / NK, ku = hk - h * NK;
            float pv = d_vals[h * TOPK + jj * NK + ku];
            float sg = 1.0f / (1.0f + expf(-pv));
            acc += m * sg;
        }
    }
    atomicAdd(&d_pooled[jj * DIM + t], acc);
}

// out = log_softmax((pooled/4000) @ W2)
__global__ void k_out(const float* __restrict__ W2, float* __restrict__ out) {
    __shared__ float lg[NJ * NC];
    __shared__ float red[NJ * 2];
    int t = threadIdx.x;
    if (t < NJ * NC) {
        int jj = t / NC, c = t - jj * NC;
        float sacc = 0.0f;
        for (int d = 0; d < DIM; d++)
            sacc += d_pooled[jj * DIM + d] * __ldg(&W2[d * NC + c]);
        lg[t] = sacc * (1.0f / 4000.0f);
    }
    __syncthreads();
    if (t < NJ) {
        float mx = -1e30f;
        for (int c = 0; c < NC; c++) mx = fmaxf(mx, lg[t * NC + c]);
        float se = 0.0f;
        for (int c = 0; c < NC; c++) se += expf(lg[t * NC + c] - mx);
        red[t * 2] = mx;
        red[t * 2 + 1] = logf(se);
    }
    __syncthreads();
    if (t < NJ * NC) {
        int jj = t / NC;
        out[t] = lg[t] - red[jj * 2] - red[jj * 2 + 1];
    }
}

// ---------------- host launcher ----------------
extern "C" void kernel_launch(void* const* d_in, const int* in_sizes, int n_in,
                              void* d_out, int out_size) {
    const float* x         = (const float*)d_in[0];
    const float* edge_attr = (const float*)d_in[1];
    const float* w_rank    = (const float*)d_in[2];
    const float* W1        = (const float*)d_in[3];
    const float* W2        = (const float*)d_in[4];
    const int*   ei        = (const int*)d_in[5];
    float*       out       = (float*)d_out;

    void *p_deg, *p_hist, *p_cc, *p_nc, *p_loc, *p_msg, *p_pool;
    cudaGetSymbolAddress(&p_deg,  d_deg);
    cudaGetSymbolAddress(&p_hist, d_hist);
    cudaGetSymbolAddress(&p_cc,   d_ccount);
    cudaGetSymbolAddress(&p_nc,   d_nnzcnt);
    cudaGetSymbolAddress(&p_loc,  d_locmap);
    cudaGetSymbolAddress(&p_msg,  d_msg);
    cudaGetSymbolAddress(&p_pool, d_pooled);

    cudaMemsetAsync(p_deg,  0, sizeof(int) * N_NODES);
    cudaMemsetAsync(p_hist, 0, sizeof(unsigned) * NH * NBINS);
    cudaMemsetAsync(p_cc,   0, sizeof(int) * NH);
    cudaMemsetAsync(p_nc,   0, sizeof(int));
    cudaMemsetAsync(p_loc,  0, sizeof(int) * N_NODES * NH);
    cudaMemsetAsync(p_msg,  0, sizeof(float) * NG * NK * DIM);
    cudaMemsetAsync(p_pool, 0, sizeof(float) * NJ * DIM);

    cudaFuncSetAttribute(k_sort, cudaFuncAttributeMaxDynamicSharedMemorySize,
                         CAP * (int)sizeof(unsigned long long));

    const int TB = 256;
    int gE = (N_EDGES + TB - 1) / TB;
    int gN = (N_NODES + TB - 1) / TB;

    k_deg<<<gE, TB>>>(ei);
    k_p<<<(N_NODES + 7) / 8, TB>>>(x, w_rank);
    k_scores_init<<<gN, TB>>>();
    k_scores_edges<<<gE, TB>>>(ei);
    k_hist<<<gN, TB>>>();
    k_scan<<<NH, 1024>>>();
    k_compact<<<gN, TB>>>();
    k_sort<<<NH, 1024, CAP * sizeof(unsigned long long)>>>();
    k_nnz<<<gE, TB>>>(ei, edge_attr);
    k_msg<<<2048, DIM>>>(x, W1);
    k_pooled<<<NJ * 32, DIM>>>();
    k_out<<<1, 320>>>(W2, out);
}

// round 3
// speedup vs baseline: 1.2560x; 1.2560x over previous
#include <cuda_runtime.h>
#include <math.h>
#include <stdint.h>

#define N_NODES 100000
#define N_EDGES 1000000
#define DIM     128
#define NH      4
#define NJ      8
#define NK      1000
#define NC      40
#define TOPK    8000            // NJ*NK per head
#define NBINS   65536
#define CAP     16384
#define NNZ_CAP (1<<20)
#define NG      32              // NJ*NH
#define NROWS   (NG*NK)         // 32000 msg rows

// ---------------- zeroed scratch: ONE memset covers this struct ----------------
struct Scratch {
    int            deg[N_NODES];            // in-degree
    unsigned       hist[NH * NBINS];        // per-head 16-bit-key histogram
    int            nnzcnt;
    int            nrows;
    int            pad0[2];
    unsigned short locmap[N_NODES * NH];    // 0 = absent, else rank+1
    float          acc[N_NODES * NH];       // edge-accumulated sum of q[u]
    int            flag[NROWS];             // msg-row touched flags
    float          pooled[NJ * DIM];
};
__device__ Scratch S;

// ---------------- non-zeroed scratch (fully rewritten every replay) ------------
__device__ float               d_p[N_NODES * NH];      // x @ w_rank
__device__ float               d_q[N_NODES * NH];      // p * rsqrt(deg)
__device__ float               d_scores[N_NODES * NH]; // final scores
__device__ unsigned            d_pref[NH * NBINS];     // descending exclusive prefix
__device__ int                 d_B[NH];                // threshold bin
__device__ int                 d_cnt[NH];              // candidate count
__device__ unsigned long long  d_cbuf[NH * CAP];       // bin-grouped candidate keys
__device__ int                 d_sidx[NH * TOPK];
__device__ float               d_vals[NH * TOPK];
__device__ uint2               d_nnz[NNZ_CAP];
__device__ int                 d_rows[NROWS];          // touched msg rows
__device__ float               d_msg[NROWS * DIM];     // self-cleaning (BSS zero)

// ---------------- helpers ----------------
__device__ __forceinline__ unsigned flip_key(float f) {
    unsigned u = __float_as_uint(f);
    return (u >> 31) ? ~u : (u | 0x80000000u);
}

// ---------------- kernels ----------------

// in-degree
__global__ void k_deg(const int* __restrict__ ei) {
    int e = blockIdx.x * blockDim.x + threadIdx.x;
    if (e < N_EDGES) atomicAdd(&S.deg[__ldg(&ei[N_EDGES + e])], 1);
}

// p = x @ w_rank  (warp per node)
__global__ void k_p(const float* __restrict__ x, const float* __restrict__ wr) {
    int warp = (blockIdx.x * blockDim.x + threadIdx.x) >> 5;
    int lane = threadIdx.x & 31;
    if (warp >= N_NODES) return;
    const float* xr = x + (size_t)warp * DIM;
    float a0 = 0, a1 = 0, a2 = 0, a3 = 0;
    #pragma unroll
    for (int c0 = 0; c0 < DIM; c0 += 32) {
        int c = c0 + lane;
        float xv = __ldg(&xr[c]);
        float4 w4 = __ldg(reinterpret_cast<const float4*>(&wr[c * NH]));
        a0 += xv * w4.x; a1 += xv * w4.y; a2 += xv * w4.z; a3 += xv * w4.w;
    }
    #pragma unroll
    for (int o = 16; o; o >>= 1) {
        a0 += __shfl_down_sync(0xFFFFFFFFu, a0, o);
        a1 += __shfl_down_sync(0xFFFFFFFFu, a1, o);
        a2 += __shfl_down_sync(0xFFFFFFFFu, a2, o);
        a3 += __shfl_down_sync(0xFFFFFFFFu, a3, o);
    }
    if (lane == 0)
        *reinterpret_cast<float4*>(&d_p[warp * NH]) = make_float4(a0, a1, a2, a3);
}

// q = p * rsqrt(deg)
__global__ void k_q() {
    int n = blockIdx.x * blockDim.x + threadIdx.x;
    if (n >= N_NODES) return;
    float rs = rsqrtf((float)S.deg[n] + 1.0f);
    float4 p4 = *reinterpret_cast<const float4*>(&d_p[n * NH]);
    *reinterpret_cast<float4*>(&d_q[n * NH]) =
        make_float4(p4.x * rs, p4.y * rs, p4.z * rs, p4.w * rs);
}

// acc[v] += q[u]   (no deg gathers, no rsqrt in the hot loop)
__global__ void k_edge(const int* __restrict__ ei) {
    int e = blockIdx.x * blockDim.x + threadIdx.x;
    if (e >= N_EDGES) return;
    int u = __ldg(&ei[e]), v = __ldg(&ei[N_EDGES + e]);
    float4 q4 = __ldg(reinterpret_cast<const float4*>(&d_q[u * NH]));
    atomicAdd(&S.acc[v * NH + 0], q4.x);
    atomicAdd(&S.acc[v * NH + 1], q4.y);
    atomicAdd(&S.acc[v * NH + 2], q4.z);
    atomicAdd(&S.acc[v * NH + 3], q4.w);
}

// scores[v] = p[v]/deg + rsqrt(deg)*acc[v]; histogram top-16 bits
__global__ void k_histfin() {
    int n = blockIdx.x * blockDim.x + threadIdx.x;
    if (n >= N_NODES) return;
    float dv  = (float)S.deg[n] + 1.0f;
    float inv = 1.0f / dv;
    float rs  = rsqrtf(dv);
    float4 p4 = *reinterpret_cast<const float4*>(&d_p[n * NH]);
    float4 a4 = *reinterpret_cast<const float4*>(&S.acc[n * NH]);
    float4 s4 = make_float4(p4.x * inv + rs * a4.x, p4.y * inv + rs * a4.y,
                            p4.z * inv + rs * a4.z, p4.w * inv + rs * a4.w);
    *reinterpret_cast<float4*>(&d_scores[n * NH]) = s4;
    atomicAdd(&S.hist[0 * NBINS + (flip_key(s4.x) >> 16)], 1u);
    atomicAdd(&S.hist[1 * NBINS + (flip_key(s4.y) >> 16)], 1u);
    atomicAdd(&S.hist[2 * NBINS + (flip_key(s4.z) >> 16)], 1u);
    atomicAdd(&S.hist[3 * NBINS + (flip_key(s4.w) >> 16)], 1u);
}

// per-head descending exclusive prefix over all bins + threshold bin B + count
__global__ void k_scanpref() {
    __shared__ unsigned ss[1024];
    __shared__ int      posC[1024];
    __shared__ unsigned cntC[1024];
    int h = blockIdx.x, t = threadIdx.x;
    int base = h * NBINS;
    // chunk sum (bins descending: position pos=t*64+k -> bin NBINS-1-pos)
    unsigned csum = 0;
    for (int k = 0; k < 64; k++)
        csum += S.hist[base + (NBINS - 1 - (t * 64 + k))];
    ss[t] = csum;
    __syncthreads();
    // inclusive Hillis-Steele scan over 1024 chunk sums
    for (int off = 1; off < 1024; off <<= 1) {
        unsigned v = (t >= off) ? ss[t - off] : 0u;
        __syncthreads();
        ss[t] += v;
        __syncthreads();
    }
    unsigned excl = (t > 0) ? ss[t - 1] : 0u;
    // write per-bin exclusive descending prefix; track threshold crossing
    unsigned run = excl;
    int pos = -1; unsigned cnt = 0;
    for (int k = 0; k < 64; k++) {
        int bin = NBINS - 1 - (t * 64 + k);
        unsigned hv = S.hist[base + bin];
        d_pref[base + bin] = run;
        if (run < TOPK) { pos = t * 64 + k; cnt = run + hv; }
        run += hv;
    }
    posC[t] = pos; cntC[t] = cnt;
    __syncthreads();
    if (t == 0) {
        int best = -1; unsigned bc = 0;
        for (int i = 0; i < 1024; i++)
            if (posC[i] > best) { best = posC[i]; bc = cntC[i]; }
        d_B[h]   = NBINS - 1 - best;
        d_cnt[h] = (int)bc;
    }
}

// counting-sort candidates into bin segments (fetch-add on prefix gives slot)
__global__ void k_compact() {
    int n = blockIdx.x * blockDim.x + threadIdx.x;
    if (n >= N_NODES) return;
    float4 s4 = *reinterpret_cast<const float4*>(&d_scores[n * NH]);
    float sv[4] = {s4.x, s4.y, s4.z, s4.w};
    #pragma unroll
    for (int h = 0; h < NH; h++) {
        unsigned key = flip_key(sv[h]);
        int bin = (int)(key >> 16);
        if (bin >= d_B[h]) {
            unsigned slot = atomicAdd(&d_pref[h * NBINS + bin], 1u);
            d_cbuf[h * CAP + slot] =
                ((unsigned long long)key << 32) | (unsigned)(~(unsigned)n);
        }
    }
}

// exact rank = bin base + #greater-in-segment; emit sidx/vals/locmap
__global__ void k_rank() {
    int tid = blockIdx.x * blockDim.x + threadIdx.x;
    int h = tid / CAP, slot = tid % CAP;
    if (h >= NH || slot >= d_cnt[h]) return;
    unsigned long long key = d_cbuf[h * CAP + slot];
    int bin = (int)(key >> 48);
    unsigned segEnd   = d_pref[h * NBINS + bin];            // post-compact = base+occ
    unsigned occ      = S.hist[h * NBINS + bin];
    unsigned segStart = segEnd - occ;
    int rank = (int)segStart;
    for (unsigned j = segStart; j < segEnd; j++)
        if (d_cbuf[h * CAP + j] > key) rank++;
    if (rank < TOPK) {
        unsigned key32 = (unsigned)(key >> 32);
        int n = (int)(~(unsigned)key);
        float f = __uint_as_float((key32 & 0x80000000u) ? (key32 & 0x7FFFFFFFu)
                                                        : ~key32);
        d_sidx[h * TOPK + rank] = n;
        d_vals[h * TOPK + rank] = f;
        S.locmap[n * NH + h] = (unsigned short)(rank + 1);
    }
}

// edge pass: emit sparse adj triples (g, ku, kv, w)
__global__ void k_nnz(const int* __restrict__ ei, const float* __restrict__ ea) {
    int e = blockIdx.x * blockDim.x + threadIdx.x;
    if (e >= N_EDGES) return;
    int u = __ldg(&ei[e]), v = __ldg(&ei[N_EDGES + e]);
    ushort4 lu4 = __ldg(reinterpret_cast<const ushort4*>(&S.locmap[u * NH]));
    ushort4 lv4 = __ldg(reinterpret_cast<const ushort4*>(&S.locmap[v * NH]));
    int lus[4] = {lu4.x, lu4.y, lu4.z, lu4.w};
    int lvs[4] = {lv4.x, lv4.y, lv4.z, lv4.w};
    #pragma unroll
    for (int h = 0; h < NH; h++) {
        int lu = lus[h], lv = lvs[h];
        if (lu == 0 || lv == 0) continue;
        int pu = lu - 1, pv = lv - 1;
        int jju = pu / NK;
        if (jju != pv / NK) continue;
        float w = __ldg(&ea[e]);
        int g  = jju * NH + h;
        int ku = pu - jju * NK;
        int kv = pv - jju * NK;
        int pos = atomicAdd(&S.nnzcnt, 1);
        if (pos < NNZ_CAP)
            d_nnz[pos] = make_uint2(((unsigned)g << 20) | ((unsigned)ku << 10) | (unsigned)kv,
                                    __float_as_uint(w));
    }
}

// sparse msg: msg[g,ku,:] += w * (x[node(g,kv)] @ W1); register touched rows
__global__ void k_msg(const float* __restrict__ x, const float* __restrict__ W1) {
    __shared__ float xs[DIM];
    int cnt = min(S.nnzcnt, NNZ_CAP);
    int t = threadIdx.x;
    for (int e = blockIdx.x; e < cnt; e += gridDim.x) {
        uint2 en = d_nnz[e];
        int packed = (int)en.x;
        float w = __uint_as_float(en.y);
        int g = packed >> 20, ku = (packed >> 10) & 1023, kv = packed & 1023;
        int hh = g & 3, jj = g >> 2;
        int row = g * NK + ku;
        int node = d_sidx[hh * TOPK + jj * NK + kv];
        if (t == 0) {
            if (atomicExch(&S.flag[row], 1) == 0) {
                int rp = atomicAdd(&S.nrows, 1);
                d_rows[rp] = row;
            }
        }
        __syncthreads();
        xs[t] = __ldg(&x[(size_t)node * DIM + t]);
        __syncthreads();
        float acc = 0.0f;
        #pragma unroll 8
        for (int c = 0; c < DIM; c++) acc += xs[c] * __ldg(&W1[c * DIM + t]);
        atomicAdd(&d_msg[(size_t)row * DIM + t], w * acc);
        __syncthreads();
    }
}

// pooled[jj] += relu(msg_row)*sigmoid(perm); then clear the row (self-cleaning)
__global__ void k_pooled() {
    int t = threadIdx.x;
    int nr = S.nrows;
    for (int r = blockIdx.x; r < nr; r += gridDim.x) {
        int row = d_rows[r];
        int g = row / NK, ku = row - g * NK;
        int h = g & 3, jj = g >> 2;
        float pv = d_vals[h * TOPK + jj * NK + ku];
        float sg = 1.0f / (1.0f + expf(-pv));
        float m = d_msg[(size_t)row * DIM + t];
        if (m > 0.0f) atomicAdd(&S.pooled[jj * DIM + t], m * sg);
        d_msg[(size_t)row * DIM + t] = 0.0f;   // restore invariant
    }
}

// out = log_softmax((pooled/4000) @ W2)
__global__ void k_out(const float* __restrict__ W2, float* __restrict__ out) {
    __shared__ float lg[NJ * NC];
    __shared__ float red[NJ * 2];
    int t = threadIdx.x;
    if (t < NJ * NC) {
        int jj = t / NC, c = t - jj * NC;
        float sacc = 0.0f;
        for (int d = 0; d < DIM; d++)
            sacc += S.pooled[jj * DIM + d] * __ldg(&W2[d * NC + c]);
        lg[t] = sacc * (1.0f / 4000.0f);
    }
    __syncthreads();
    if (t < NJ) {
        float mx = -1e30f;
        for (int c = 0; c < NC; c++) mx = fmaxf(mx, lg[t * NC + c]);
        float se = 0.0f;
        for (int c = 0; c < NC; c++) se += expf(lg[t * NC + c] - mx);
        red[t * 2] = mx;
        red[t * 2 + 1] = logf(se);
    }
    __syncthreads();
    if (t < NJ * NC) {
        int jj = t / NC;
        out[t] = lg[t] - red[jj * 2] - red[jj * 2 + 1];
    }
}

// ---------------- host launcher ----------------
extern "C" void kernel_launch(void* const* d_in, const int* in_sizes, int n_in,
                              void* d_out, int out_size) {
    const float* x         = (const float*)d_in[0];
    const float* edge_attr = (const float*)d_in[1];
    const float* w_rank    = (const float*)d_in[2];
    const float* W1        = (const float*)d_in[3];
    const float* W2        = (const float*)d_in[4];
    const int*   ei        = (const int*)d_in[5];
    float*       out       = (float*)d_out;

    void* pS;
    cudaGetSymbolAddress(&pS, S);
    cudaMemsetAsync(pS, 0, sizeof(Scratch));

    const int TB = 256;
    int gE = (N_EDGES + TB - 1) / TB;
    int gN = (N_NODES + TB - 1) / TB;

    k_deg<<<gE, TB>>>(ei);
    k_p<<<(N_NODES + 7) / 8, TB>>>(x, w_rank);
    k_q<<<gN, TB>>>();
    k_edge<<<gE, TB>>>(ei);
    k_histfin<<<gN, TB>>>();
    k_scanpref<<<NH, 1024>>>();
    k_compact<<<gN, TB>>>();
    k_rank<<<(NH * CAP) / TB, TB>>>();
    k_nnz<<<gE, TB>>>(ei, edge_attr);
    k_msg<<<2048, DIM>>>(x, W1);
    k_pooled<<<512, DIM>>>();
    k_out<<<1, 320>>>(W2, out);
}

// round 4
// speedup vs baseline: 1.2738x; 1.0141x over previous
#include <cuda_runtime.h>
#include <math.h>
#include <stdint.h>

#define N_NODES 100000
#define N_EDGES 1000000
#define DIM     128
#define NH      4
#define NJ      8
#define NK      1000
#define NC      40
#define TOPK    8000            // NJ*NK per head
#define NBINS   65536
#define CAP     16384
#define NNZ_CAP (1<<20)
#define NG      32              // NJ*NH
#define NROWS   (NG*NK)         // 32000 msg rows

#define GRID1   592             // K1: 4 blocks/SM x 148 (256 thr)
#define GRID2   148             // K2: 1 block/SM (1024 thr)
#define GRID3   592             // K3: 4 blocks/SM (128 thr)

// ---------------- zeroed scratch: ONE memset covers this struct ----------------
struct Scratch {
    int            deg[N_NODES];            // in-degree
    unsigned       hist[NH * NBINS];        // per-head 16-bit-key histogram
    int            nnzcnt;
    int            nrows;
    int            pad0[2];
    unsigned short locmap[N_NODES * NH];    // 0 = absent, else rank+1
    float          acc[N_NODES * NH];       // edge-accumulated sum of q[u]
    int            flag[NROWS];             // msg-row touched flags
    float          pooled[NJ * DIM];
};
__device__ Scratch S;

// ---------------- non-zeroed scratch (rewritten or self-restoring) -------------
__device__ float               d_p[N_NODES * NH];      // x @ w_rank
__device__ float               d_q[N_NODES * NH];      // p * rsqrt(deg)
__device__ float               d_scores[N_NODES * NH]; // final scores
__device__ unsigned            d_pref[NH * NBINS];     // descending exclusive prefix
__device__ int                 d_B[NH];                // threshold bin
__device__ int                 d_cnt[NH];              // candidate count
__device__ unsigned long long  d_cbuf[NH * CAP];       // bin-grouped candidate keys
__device__ int                 d_sidx[NH * TOPK];
__device__ float               d_vals[NH * TOPK];
__device__ uint2               d_nnz[NNZ_CAP];
__device__ int                 d_rows[NROWS];          // touched msg rows
__device__ float               d_msg[NROWS * DIM];     // self-cleaning (BSS zero)

// ---------------- grid-wide software barrier (all blocks co-resident) ----------
__device__ unsigned            bar_cnt = 0;
__device__ volatile unsigned   bar_gen = 0;

__device__ __forceinline__ void gridbar() {
    __syncthreads();
    if (threadIdx.x == 0) {
        unsigned gen = bar_gen;
        __threadfence();
        if (atomicAdd(&bar_cnt, 1u) == gridDim.x - 1u) {
            bar_cnt = 0;
            __threadfence();
            bar_gen = gen + 1u;
        } else {
            while (bar_gen == gen) __nanosleep(32);
        }
        __threadfence();
    }
    __syncthreads();
}

// ---------------- helpers ----------------
__device__ __forceinline__ unsigned flip_key(float f) {
    unsigned u = __float_as_uint(f);
    return (u >> 31) ? ~u : (u | 0x80000000u);
}

// ================= K1: deg||p -> q -> edge -> histfin =========================
__global__ void __launch_bounds__(256, 4)
K1(const float* __restrict__ x, const float* __restrict__ wr,
   const int* __restrict__ ei) {
    const int gtid = blockIdx.x * 256 + threadIdx.x;
    const int gth  = GRID1 * 256;

    // phase A1: in-degree
    for (int e = gtid; e < N_EDGES; e += gth)
        atomicAdd(&S.deg[__ldg(&ei[N_EDGES + e])], 1);

    // phase A2: p = x @ w_rank (warp per node)
    {
        int warp = gtid >> 5, nwarps = gth >> 5, lane = threadIdx.x & 31;
        for (int n = warp; n < N_NODES; n += nwarps) {
            const float* xr = x + (size_t)n * DIM;
            float a0 = 0, a1 = 0, a2 = 0, a3 = 0;
            #pragma unroll
            for (int c0 = 0; c0 < DIM; c0 += 32) {
                int c = c0 + lane;
                float xv = __ldg(&xr[c]);
                float4 w4 = __ldg(reinterpret_cast<const float4*>(&wr[c * NH]));
                a0 += xv * w4.x; a1 += xv * w4.y; a2 += xv * w4.z; a3 += xv * w4.w;
            }
            #pragma unroll
            for (int o = 16; o; o >>= 1) {
                a0 += __shfl_down_sync(0xFFFFFFFFu, a0, o);
                a1 += __shfl_down_sync(0xFFFFFFFFu, a1, o);
                a2 += __shfl_down_sync(0xFFFFFFFFu, a2, o);
                a3 += __shfl_down_sync(0xFFFFFFFFu, a3, o);
            }
            if (lane == 0)
                *reinterpret_cast<float4*>(&d_p[n * NH]) = make_float4(a0, a1, a2, a3);
        }
    }
    gridbar();

    // phase B: q = p * rsqrt(deg)
    for (int n = gtid; n < N_NODES; n += gth) {
        float rs = rsqrtf((float)S.deg[n] + 1.0f);
        float4 p4 = *reinterpret_cast<const float4*>(&d_p[n * NH]);
        *reinterpret_cast<float4*>(&d_q[n * NH]) =
            make_float4(p4.x * rs, p4.y * rs, p4.z * rs, p4.w * rs);
    }
    gridbar();

    // phase C: acc[v] += q[u]  (vector reduction, 1 op per edge)
    for (int e = gtid; e < N_EDGES; e += gth) {
        int u = __ldg(&ei[e]), v = __ldg(&ei[N_EDGES + e]);
        float4 q4 = __ldg(reinterpret_cast<const float4*>(&d_q[u * NH]));
        asm volatile("red.global.add.v4.f32 [%0], {%1, %2, %3, %4};"
                     :: "l"(&S.acc[v * NH]),
                        "f"(q4.x), "f"(q4.y), "f"(q4.z), "f"(q4.w)
                     : "memory");
    }
    gridbar();

    // phase D: scores = p/deg + rsqrt(deg)*acc; histogram top-16 bits
    for (int n = gtid; n < N_NODES; n += gth) {
        float dv  = (float)S.deg[n] + 1.0f;
        float inv = 1.0f / dv;
        float rs  = rsqrtf(dv);
        float4 p4 = *reinterpret_cast<const float4*>(&d_p[n * NH]);
        float4 a4 = *reinterpret_cast<const float4*>(&S.acc[n * NH]);
        float4 s4 = make_float4(p4.x * inv + rs * a4.x, p4.y * inv + rs * a4.y,
                                p4.z * inv + rs * a4.z, p4.w * inv + rs * a4.w);
        *reinterpret_cast<float4*>(&d_scores[n * NH]) = s4;
        atomicAdd(&S.hist[0 * NBINS + (flip_key(s4.x) >> 16)], 1u);
        atomicAdd(&S.hist[1 * NBINS + (flip_key(s4.y) >> 16)], 1u);
        atomicAdd(&S.hist[2 * NBINS + (flip_key(s4.z) >> 16)], 1u);
        atomicAdd(&S.hist[3 * NBINS + (flip_key(s4.w) >> 16)], 1u);
    }
}

// ================= K2: scanpref -> compact -> rank ============================
__global__ void __launch_bounds__(1024, 1)
K2() {
    __shared__ unsigned ss[1024];
    __shared__ int      posC[1024];
    __shared__ unsigned cntC[1024];
    const int gtid = blockIdx.x * 1024 + threadIdx.x;
    const int gth  = GRID2 * 1024;
    const int t = threadIdx.x;

    // phase A: per-head descending prefix + threshold (blocks 0..NH-1)
    if (blockIdx.x < NH) {
        int h = blockIdx.x;
        int base = h * NBINS;
        unsigned csum = 0;
        for (int k = 0; k < 64; k++)
            csum += S.hist[base + (NBINS - 1 - (t * 64 + k))];
        ss[t] = csum;
        __syncthreads();
        for (int off = 1; off < 1024; off <<= 1) {
            unsigned v = (t >= off) ? ss[t - off] : 0u;
            __syncthreads();
            ss[t] += v;
            __syncthreads();
        }
        unsigned run = (t > 0) ? ss[t - 1] : 0u;
        int pos = -1; unsigned cnt = 0;
        for (int k = 0; k < 64; k++) {
            int bin = NBINS - 1 - (t * 64 + k);
            unsigned hv = S.hist[base + bin];
            d_pref[base + bin] = run;
            if (run < TOPK) { pos = t * 64 + k; cnt = run + hv; }
            run += hv;
        }
        posC[t] = pos; cntC[t] = cnt;
        __syncthreads();
        // parallel argmax over chunk positions
        for (int off = 512; off; off >>= 1) {
            if (t < off && posC[t + off] > posC[t]) {
                posC[t] = posC[t + off]; cntC[t] = cntC[t + off];
            }
            __syncthreads();
        }
        if (t == 0) {
            d_B[h]   = NBINS - 1 - posC[0];
            d_cnt[h] = (int)cntC[0];
        }
    }
    gridbar();

    // phase B: counting-sort candidates into bin segments
    for (int n = gtid; n < N_NODES; n += gth) {
        float4 s4 = *reinterpret_cast<const float4*>(&d_scores[n * NH]);
        float sv[4] = {s4.x, s4.y, s4.z, s4.w};
        #pragma unroll
        for (int h = 0; h < NH; h++) {
            unsigned key = flip_key(sv[h]);
            int bin = (int)(key >> 16);
            if (bin >= d_B[h]) {
                unsigned slot = atomicAdd(&d_pref[h * NBINS + bin], 1u);
                if (slot < CAP)
                    d_cbuf[h * CAP + slot] =
                        ((unsigned long long)key << 32) | (unsigned)(~(unsigned)n);
            }
        }
    }
    gridbar();

    // phase C: exact rank = bin base + #greater-in-segment
    for (int i = gtid; i < NH * CAP; i += gth) {
        int h = i / CAP, slot = i % CAP;
        if (slot >= d_cnt[h]) continue;
        unsigned long long key = d_cbuf[h * CAP + slot];
        int bin = (int)(key >> 48);
        unsigned segEnd   = d_pref[h * NBINS + bin];   // post-compact = base+occ
        unsigned occ      = S.hist[h * NBINS + bin];
        unsigned segStart = segEnd - occ;
        int rank = (int)segStart;
        for (unsigned j = segStart; j < segEnd; j++)
            if (d_cbuf[h * CAP + j] > key) rank++;
        if (rank < TOPK) {
            unsigned key32 = (unsigned)(key >> 32);
            int n = (int)(~(unsigned)key);
            float f = __uint_as_float((key32 & 0x80000000u) ? (key32 & 0x7FFFFFFFu)
                                                            : ~key32);
            d_sidx[h * TOPK + rank] = n;
            d_vals[h * TOPK + rank] = f;
            S.locmap[n * NH + h] = (unsigned short)(rank + 1);
        }
    }
}

// ================= K3: nnz -> msg -> pooled -> out ============================
__global__ void __launch_bounds__(128, 4)
K3(const int* __restrict__ ei, const float* __restrict__ ea,
   const float* __restrict__ x, const float* __restrict__ W1,
   const float* __restrict__ W2, float* __restrict__ out) {
    __shared__ float xs[DIM];
    __shared__ float lg[NJ * NC];
    __shared__ float red2[NJ * 2];
    const int gtid = blockIdx.x * 128 + threadIdx.x;
    const int gth  = GRID3 * 128;
    const int t = threadIdx.x;

    // phase A: sparse adj triples
    for (int e = gtid; e < N_EDGES; e += gth) {
        int u = __ldg(&ei[e]), v = __ldg(&ei[N_EDGES + e]);
        ushort4 lu4 = __ldg(reinterpret_cast<const ushort4*>(&S.locmap[u * NH]));
        ushort4 lv4 = __ldg(reinterpret_cast<const ushort4*>(&S.locmap[v * NH]));
        int lus[4] = {lu4.x, lu4.y, lu4.z, lu4.w};
        int lvs[4] = {lv4.x, lv4.y, lv4.z, lv4.w};
        #pragma unroll
        for (int h = 0; h < NH; h++) {
            int lu = lus[h], lv = lvs[h];
            if (lu == 0 || lv == 0) continue;
            int pu = lu - 1, pv = lv - 1;
            int jju = pu / NK;
            if (jju != pv / NK) continue;
            float w = __ldg(&ea[e]);
            int g  = jju * NH + h;
            int ku = pu - jju * NK;
            int kv = pv - jju * NK;
            int pos = atomicAdd(&S.nnzcnt, 1);
            if (pos < NNZ_CAP)
                d_nnz[pos] = make_uint2(((unsigned)g << 20) | ((unsigned)ku << 10) | (unsigned)kv,
                                        __float_as_uint(w));
        }
    }
    gridbar();

    // phase B: msg[g,ku,:] += w * (x[node(g,kv)] @ W1)
    {
        int cnt = min(S.nnzcnt, NNZ_CAP);
        for (int e = blockIdx.x; e < cnt; e += gridDim.x) {
            uint2 en = d_nnz[e];
            int packed = (int)en.x;
            float w = __uint_as_float(en.y);
            int g = packed >> 20, ku = (packed >> 10) & 1023, kv = packed & 1023;
            int hh = g & 3, jj = g >> 2;
            int row = g * NK + ku;
            int node = d_sidx[hh * TOPK + jj * NK + kv];
            if (t == 0) {
                if (atomicExch(&S.flag[row], 1) == 0) {
                    int rp = atomicAdd(&S.nrows, 1);
                    d_rows[rp] = row;
                }
            }
            __syncthreads();
            xs[t] = __ldg(&x[(size_t)node * DIM + t]);
            __syncthreads();
            float acc = 0.0f;
            #pragma unroll 8
            for (int c = 0; c < DIM; c++) acc += xs[c] * __ldg(&W1[c * DIM + t]);
            atomicAdd(&d_msg[(size_t)row * DIM + t], w * acc);
            __syncthreads();
        }
    }
    gridbar();

    // phase C: pooled += relu(msg_row)*sigmoid(perm); clear row (self-cleaning)
    {
        int nr = S.nrows;
        for (int r = blockIdx.x; r < nr; r += gridDim.x) {
            int row = d_rows[r];
            int g = row / NK, ku = row - g * NK;
            int h = g & 3, jj = g >> 2;
            float pv = d_vals[h * TOPK + jj * NK + ku];
            float sg = 1.0f / (1.0f + expf(-pv));
            float m = d_msg[(size_t)row * DIM + t];
            if (m > 0.0f) atomicAdd(&S.pooled[jj * DIM + t], m * sg);
            d_msg[(size_t)row * DIM + t] = 0.0f;
        }
    }
    gridbar();

    // phase D: out = log_softmax((pooled/4000) @ W2)  (block 0 only)
    if (blockIdx.x == 0) {
        for (int i = t; i < NJ * NC; i += 128) {
            int jj = i / NC, c = i - jj * NC;
            float sacc = 0.0f;
            for (int d = 0; d < DIM; d++)
                sacc += S.pooled[jj * DIM + d] * __ldg(&W2[d * NC + c]);
            lg[i] = sacc * (1.0f / 4000.0f);
        }
        __syncthreads();
        if (t < NJ) {
            float mx = -1e30f;
            for (int c = 0; c < NC; c++) mx = fmaxf(mx, lg[t * NC + c]);
            float se = 0.0f;
            for (int c = 0; c < NC; c++) se += expf(lg[t * NC + c] - mx);
            red2[t * 2] = mx;
            red2[t * 2 + 1] = logf(se);
        }
        __syncthreads();
        for (int i = t; i < NJ * NC; i += 128) {
            int jj = i / NC;
            out[i] = lg[i] - red2[jj * 2] - red2[jj * 2 + 1];
        }
    }
}

// ---------------- host launcher ----------------
extern "C" void kernel_launch(void* const* d_in, const int* in_sizes, int n_in,
                              void* d_out, int out_size) {
    const float* x         = (const float*)d_in[0];
    const float* edge_attr = (const float*)d_in[1];
    const float* w_rank    = (const float*)d_in[2];
    const float* W1        = (const float*)d_in[3];
    const float* W2        = (const float*)d_in[4];
    const int*   ei        = (const int*)d_in[5];
    float*       out       = (float*)d_out;

    void* pS;
    cudaGetSymbolAddress(&pS, S);
    cudaMemsetAsync(pS, 0, sizeof(Scratch));

    K1<<<GRID1, 256>>>(x, w_rank, ei);
    K2<<<GRID2, 1024>>>();
    K3<<<GRID3, 128>>>(ei, edge_attr, x, W1, W2, out);
}

// round 5
// speedup vs baseline: 1.5997x; 1.2559x over previous
#include <cuda_runtime.h>
#include <math.h>
#include <stdint.h>

#define N_NODES 100000
#define N_EDGES 1000000
#define DIM     128
#define NH      4
#define NJ      8
#define NK      1000
#define NC      40
#define TOPK    8000            // NJ*NK per head
#define NBINS   65536
#define CAP     16384
#define NNZ_CAP (1<<20)
#define NG      32              // NJ*NH
#define NROWS   (NG*NK)         // 32000 msg rows

#define GRID    592             // 4 blocks/SM x 148 SMs (must be 1 wave)
#define TPB     256
#define GTH     (GRID*TPB)

// ---------------- zeroed-at-kernel-start scratch (phase 0) --------------------
struct __align__(16) Scratch {
    int            deg[N_NODES];            // in-degree
    unsigned       hist[NH * NBINS];        // per-head 16-bit-key histogram
    int            nnzcnt;
    int            nrows;
    int            pad0[2];
    unsigned short locmap[N_NODES * NH];    // 0 = absent, else rank+1
    float          acc[N_NODES * NH];       // edge-accumulated sum of q[u]
    int            flag[NROWS];             // msg-row touched flags
    float          pooled[NJ * DIM];
};
__device__ Scratch S;
static_assert(sizeof(Scratch) % 16 == 0, "16B multiple");

// ---------------- other scratch (fully rewritten or self-restoring) -----------
__device__ float               d_p[N_NODES * NH];      // x @ w_rank
__device__ float               d_q[N_NODES * NH];      // p * rsqrt(deg)
__device__ float               d_scores[N_NODES * NH]; // final scores
__device__ unsigned            d_pref[NH * NBINS];     // descending exclusive prefix
__device__ int                 d_B[NH];                // threshold bin
__device__ int                 d_cnt[NH];              // candidate count
__device__ unsigned long long  d_cbuf[NH * CAP];       // bin-grouped candidate keys
__device__ int                 d_sidx[NH * TOPK];
__device__ float               d_vals[NH * TOPK];
__device__ uint2               d_nnz[NNZ_CAP];
__device__ int                 d_rows[NROWS];          // touched msg rows
__device__ float               d_msg[NROWS * DIM];     // self-cleaning (BSS zero)

// ---------------- grid-wide software barrier (single co-resident wave) --------
__device__ unsigned            bar_cnt = 0;
__device__ volatile unsigned   bar_gen = 0;

__device__ __forceinline__ void gridbar() {
    __syncthreads();
    if (threadIdx.x == 0) {
        unsigned gen = bar_gen;
        __threadfence();
        if (atomicAdd(&bar_cnt, 1u) == (unsigned)(GRID - 1)) {
            bar_cnt = 0;
            __threadfence();
            bar_gen = gen + 1u;
        } else {
            while (bar_gen == gen) __nanosleep(64);
        }
        __threadfence();
    }
    __syncthreads();
}

__device__ __forceinline__ unsigned flip_key(float f) {
    unsigned u = __float_as_uint(f);
    return (u >> 31) ? ~u : (u | 0x80000000u);
}

// ================= THE kernel ================================================
__global__ void __launch_bounds__(TPB, 4)
K(const float* __restrict__ x, const float* __restrict__ wr,
  const int* __restrict__ ei, const float* __restrict__ ea,
  const float* __restrict__ W1, const float* __restrict__ W2,
  float* __restrict__ out) {
    __shared__ float sbuf[768];
    const int gtid = blockIdx.x * TPB + threadIdx.x;
    const int t = threadIdx.x;

    // ---- phase 0: zero scratch struct ----
    {
        int4* ps = reinterpret_cast<int4*>(&S);
        const int n16 = (int)(sizeof(Scratch) / 16);
        for (int i = gtid; i < n16; i += GTH) ps[i] = make_int4(0, 0, 0, 0);
    }
    gridbar();

    // ---- phase 1: in-degree atomics + p = x @ w_rank (thread per node) ----
    for (int e = gtid; e < N_EDGES; e += GTH)
        atomicAdd(&S.deg[__ldg(&ei[N_EDGES + e])], 1);
    {
        float* ws = sbuf;                         // w_rank: 512 floats
        for (int i = t; i < DIM * NH; i += TPB) ws[i] = __ldg(&wr[i]);
        __syncthreads();
        for (int n = gtid; n < N_NODES; n += GTH) {
            const float4* xr = reinterpret_cast<const float4*>(x + (size_t)n * DIM);
            float a0 = 0, a1 = 0, a2 = 0, a3 = 0;
            #pragma unroll 8
            for (int c4 = 0; c4 < DIM / 4; c4++) {
                float4 xv = __ldg(&xr[c4]);
                int b = c4 * 16;
                a0 += xv.x * ws[b+0] + xv.y * ws[b+4] + xv.z * ws[b+8]  + xv.w * ws[b+12];
                a1 += xv.x * ws[b+1] + xv.y * ws[b+5] + xv.z * ws[b+9]  + xv.w * ws[b+13];
                a2 += xv.x * ws[b+2] + xv.y * ws[b+6] + xv.z * ws[b+10] + xv.w * ws[b+14];
                a3 += xv.x * ws[b+3] + xv.y * ws[b+7] + xv.z * ws[b+11] + xv.w * ws[b+15];
            }
            *reinterpret_cast<float4*>(&d_p[n * NH]) = make_float4(a0, a1, a2, a3);
        }
    }
    gridbar();

    // ---- phase 2: q = p * rsqrt(deg) ----
    for (int n = gtid; n < N_NODES; n += GTH) {
        float rs = rsqrtf((float)S.deg[n] + 1.0f);
        float4 p4 = *reinterpret_cast<const float4*>(&d_p[n * NH]);
        *reinterpret_cast<float4*>(&d_q[n * NH]) =
            make_float4(p4.x * rs, p4.y * rs, p4.z * rs, p4.w * rs);
    }
    gridbar();

    // ---- phase 3: acc[v] += q[u]  (one vector reduction per edge) ----
    for (int e = gtid; e < N_EDGES; e += GTH) {
        int u = __ldg(&ei[e]), v = __ldg(&ei[N_EDGES + e]);
        float4 q4 = __ldg(reinterpret_cast<const float4*>(&d_q[u * NH]));
        asm volatile("red.global.add.v4.f32 [%0], {%1, %2, %3, %4};"
                     :: "l"(&S.acc[v * NH]),
                        "f"(q4.x), "f"(q4.y), "f"(q4.z), "f"(q4.w)
                     : "memory");
    }
    gridbar();

    // ---- phase 4: scores = p/deg + rsqrt(deg)*acc; histogram top-16 bits ----
    for (int n = gtid; n < N_NODES; n += GTH) {
        float dv  = (float)S.deg[n] + 1.0f;
        float inv = 1.0f / dv;
        float rs  = rsqrtf(dv);
        float4 p4 = *reinterpret_cast<const float4*>(&d_p[n * NH]);
        float4 a4 = *reinterpret_cast<const float4*>(&S.acc[n * NH]);
        float4 s4 = make_float4(p4.x * inv + rs * a4.x, p4.y * inv + rs * a4.y,
                                p4.z * inv + rs * a4.z, p4.w * inv + rs * a4.w);
        *reinterpret_cast<float4*>(&d_scores[n * NH]) = s4;
        atomicAdd(&S.hist[0 * NBINS + (flip_key(s4.x) >> 16)], 1u);
        atomicAdd(&S.hist[1 * NBINS + (flip_key(s4.y) >> 16)], 1u);
        atomicAdd(&S.hist[2 * NBINS + (flip_key(s4.z) >> 16)], 1u);
        atomicAdd(&S.hist[3 * NBINS + (flip_key(s4.w) >> 16)], 1u);
    }
    gridbar();

    // ---- phase 5: per-head descending prefix + threshold (blocks 0..3) ----
    if (blockIdx.x < NH) {
        unsigned* ss   = reinterpret_cast<unsigned*>(sbuf);
        int*      posC = reinterpret_cast<int*>(sbuf + 256);
        unsigned* cntC = reinterpret_cast<unsigned*>(sbuf + 512);
        int h = blockIdx.x, base = h * NBINS;
        unsigned csum = 0;
        for (int k = 0; k < 256; k++)
            csum += S.hist[base + (NBINS - 1 - (t * 256 + k))];
        ss[t] = csum;
        __syncthreads();
        for (int off = 1; off < 256; off <<= 1) {
            unsigned v = (t >= off) ? ss[t - off] : 0u;
            __syncthreads();
            ss[t] += v;
            __syncthreads();
        }
        unsigned run = (t > 0) ? ss[t - 1] : 0u;
        int pos = -1; unsigned cnt = 0;
        for (int k = 0; k < 256; k++) {
            int bin = NBINS - 1 - (t * 256 + k);
            unsigned hv = S.hist[base + bin];
            d_pref[base + bin] = run;
            if (run < TOPK) { pos = t * 256 + k; cnt = run + hv; }
            run += hv;
        }
        posC[t] = pos; cntC[t] = cnt;
        __syncthreads();
        for (int off = 128; off; off >>= 1) {
            if (t < off && posC[t + off] > posC[t]) {
                posC[t] = posC[t + off]; cntC[t] = cntC[t + off];
            }
            __syncthreads();
        }
        if (t == 0) { d_B[h] = NBINS - 1 - posC[0]; d_cnt[h] = (int)cntC[0]; }
    }
    gridbar();

    // ---- phase 6: counting-sort candidates into bin segments ----
    for (int n = gtid; n < N_NODES; n += GTH) {
        float4 s4 = *reinterpret_cast<const float4*>(&d_scores[n * NH]);
        float sv[4] = {s4.x, s4.y, s4.z, s4.w};
        #pragma unroll
        for (int h = 0; h < NH; h++) {
            unsigned key = flip_key(sv[h]);
            int bin = (int)(key >> 16);
            if (bin >= d_B[h]) {
                unsigned slot = atomicAdd(&d_pref[h * NBINS + bin], 1u);
                if (slot < CAP)
                    d_cbuf[h * CAP + slot] =
                        ((unsigned long long)key << 32) | (unsigned)(~(unsigned)n);
            }
        }
    }
    gridbar();

    // ---- phase 7: exact rank = bin base + #greater-in-segment ----
    for (int i = gtid; i < NH * CAP; i += GTH) {
        int h = i / CAP, slot = i % CAP;
        if (slot >= d_cnt[h]) continue;
        unsigned long long key = d_cbuf[h * CAP + slot];
        int bin = (int)(key >> 48);
        unsigned segEnd   = d_pref[h * NBINS + bin];   // post-compact = base+occ
        unsigned occ      = S.hist[h * NBINS + bin];
        unsigned segStart = segEnd - occ;
        int rank = (int)segStart;
        for (unsigned j = segStart; j < segEnd; j++)
            if (d_cbuf[h * CAP + j] > key) rank++;
        if (rank < TOPK) {
            unsigned key32 = (unsigned)(key >> 32);
            int n = (int)(~(unsigned)key);
            float f = __uint_as_float((key32 & 0x80000000u) ? (key32 & 0x7FFFFFFFu)
                                                            : ~key32);
            d_sidx[h * TOPK + rank] = n;
            d_vals[h * TOPK + rank] = f;
            S.locmap[n * NH + h] = (unsigned short)(rank + 1);
        }
    }
    gridbar();

    // ---- phase 8: sparse adj triples ----
    for (int e = gtid; e < N_EDGES; e += GTH) {
        int u = __ldg(&ei[e]), v = __ldg(&ei[N_EDGES + e]);
        ushort4 lu4 = __ldg(reinterpret_cast<const ushort4*>(&S.locmap[u * NH]));
        ushort4 lv4 = __ldg(reinterpret_cast<const ushort4*>(&S.locmap[v * NH]));
        int lus[4] = {lu4.x, lu4.y, lu4.z, lu4.w};
        int lvs[4] = {lv4.x, lv4.y, lv4.z, lv4.w};
        #pragma unroll
        for (int h = 0; h < NH; h++) {
            int lu = lus[h], lv = lvs[h];
            if (lu == 0 || lv == 0) continue;
            int pu = lu - 1, pv = lv - 1;
            int jju = pu / NK;
            if (jju != pv / NK) continue;
            float w = __ldg(&ea[e]);
            int g  = jju * NH + h;
            int ku = pu - jju * NK;
            int kv = pv - jju * NK;
            int pos = atomicAdd(&S.nnzcnt, 1);
            if (pos < NNZ_CAP)
                d_nnz[pos] = make_uint2(((unsigned)g << 20) | ((unsigned)ku << 10) | (unsigned)kv,
                                        __float_as_uint(w));
        }
    }
    gridbar();

    // ---- phase 9: msg[g,ku,:] += w * (x[node(g,kv)] @ W1)  (block per triple) ----
    {
        float* xs = sbuf;   // 128 floats
        int cnt = min(S.nnzcnt, NNZ_CAP);
        int tl = t & 127;   // lanes 0..127 compute; 128..255 mirror harmlessly
        for (int e = blockIdx.x; e < cnt; e += GRID) {
            uint2 en = d_nnz[e];
            int packed = (int)en.x;
            float w = __uint_as_float(en.y);
            int g = packed >> 20, ku = (packed >> 10) & 1023, kv = packed & 1023;
            int hh = g & 3, jj = g >> 2;
            int row = g * NK + ku;
            int node = d_sidx[hh * TOPK + jj * NK + kv];
            if (t == 0) {
                if (atomicExch(&S.flag[row], 1) == 0) {
                    int rp = atomicAdd(&S.nrows, 1);
                    d_rows[rp] = row;
                }
            }
            __syncthreads();
            if (t < DIM) xs[t] = __ldg(&x[(size_t)node * DIM + t]);
            __syncthreads();
            if (t < DIM) {
                float acc = 0.0f;
                #pragma unroll 8
                for (int c = 0; c < DIM; c++) acc += xs[c] * __ldg(&W1[c * DIM + tl]);
                atomicAdd(&d_msg[(size_t)row * DIM + tl], w * acc);
            }
            __syncthreads();
        }
    }
    gridbar();

    // ---- phase 10: pooled += relu(msg_row)*sigmoid(perm); clear row ----
    {
        int nr = S.nrows;
        for (int r = blockIdx.x; r < nr; r += GRID) {
            int row = d_rows[r];
            if (t < DIM) {
                int g = row / NK, ku = row - g * NK;
                int h = g & 3, jj = g >> 2;
                float pv = d_vals[h * TOPK + jj * NK + ku];
                float sg = 1.0f / (1.0f + expf(-pv));
                float m = d_msg[(size_t)row * DIM + t];
                if (m > 0.0f) atomicAdd(&S.pooled[jj * DIM + t], m * sg);
                d_msg[(size_t)row * DIM + t] = 0.0f;
            }
        }
    }
    gridbar();

    // ---- phase 11: out = log_softmax((pooled/4000) @ W2)  (block 0) ----
    if (blockIdx.x == 0) {
        float* lg   = sbuf;          // 320
        float* red2 = sbuf + 336;    // 16
        for (int i = t; i < NJ * NC; i += TPB) {
            int jj = i / NC, c = i - jj * NC;
            float sacc = 0.0f;
            for (int d = 0; d < DIM; d++)
                sacc += S.pooled[jj * DIM + d] * __ldg(&W2[d * NC + c]);
            lg[i] = sacc * (1.0f / 4000.0f);
        }
        __syncthreads();
        if (t < NJ) {
            float mx = -1e30f;
            for (int c = 0; c < NC; c++) mx = fmaxf(mx, lg[t * NC + c]);
            float se = 0.0f;
            for (int c = 0; c < NC; c++) se += expf(lg[t * NC + c] - mx);
            red2[t * 2] = mx;
            red2[t * 2 + 1] = logf(se);
        }
        __syncthreads();
        for (int i = t; i < NJ * NC; i += TPB) {
            int jj = i / NC;
            out[i] = lg[i] - red2[jj * 2] - red2[jj * 2 + 1];
        }
    }
}

// ---------------- host launcher: ONE node ----------------
extern "C" void kernel_launch(void* const* d_in, const int* in_sizes, int n_in,
                              void* d_out, int out_size) {
    const float* x         = (const float*)d_in[0];
    const float* edge_attr = (const float*)d_in[1];
    const float* w_rank    = (const float*)d_in[2];
    const float* W1        = (const float*)d_in[3];
    const float* W2        = (const float*)d_in[4];
    const int*   ei        = (const int*)d_in[5];
    float*       out       = (float*)d_out;

    K<<<GRID, TPB>>>(x, w_rank, ei, edge_attr, W1, W2, out);
}

// round 6
// speedup vs baseline: 1.7231x; 1.0771x over previous
#include <cuda_runtime.h>
#include <math.h>
#include <stdint.h>

#define N_NODES 100000
#define N_EDGES 1000000
#define DIM     128
#define NH      4
#define NJ      8
#define NK      1000
#define NC      40
#define TOPK    8000            // NJ*NK per head
#define NBINS   65536
#define CAP     16384
#define NG      32              // NJ*NH
#define NROWS   (NG*NK)         // 32000 msg rows

#define BPSM    6
#define GRID    (148*BPSM)      // 888 blocks, one co-resident wave
#define TPB     256
#define GTH     (GRID*TPB)

// ---------------- zeroed-at-kernel-start scratch (phase 0) --------------------
struct __align__(16) Scratch {
    int            deg[N_NODES];            // in-degree
    unsigned       hist[NH * NBINS];        // per-head 16-bit-key histogram
    int            nrows;
    int            pad0[3];
    unsigned short locmap[N_NODES * NH];    // 0 = absent, else rank+1
    float          acc[N_NODES * NH];       // edge-accumulated sum of q[u]
    int            flag[NROWS];             // msg-row touched flags
    float          pooled[NJ * DIM];
};
__device__ Scratch S;
static_assert(sizeof(Scratch) % 16 == 0, "16B multiple");

// ---------------- other scratch (fully rewritten or self-restoring) -----------
__device__ float               d_p[N_NODES * NH];      // x @ w_rank
__device__ float               d_q[N_NODES * NH];      // p * rsqrt(deg)
__device__ float               d_scores[N_NODES * NH]; // final scores
__device__ unsigned            d_pref[NH * NBINS];     // descending excl prefix (candidate range only)
__device__ int                 d_B[NH];                // threshold bin
__device__ int                 d_cnt[NH];              // candidate count
__device__ unsigned long long  d_cbuf[NH * CAP];       // bin-grouped candidate keys
__device__ int                 d_sidx[NH * TOPK];
__device__ float               d_vals[NH * TOPK];
__device__ int                 d_rows[NROWS];          // touched msg rows
__device__ float               d_msg[NROWS * DIM];     // y accumulator; self-cleaning (BSS zero)

// ---------------- grid-wide software barrier (single co-resident wave) --------
__device__ unsigned            bar_cnt = 0;
__device__ volatile unsigned   bar_gen = 0;

__device__ __forceinline__ void gridbar() {
    __syncthreads();
    if (threadIdx.x == 0) {
        unsigned gen = bar_gen;
        __threadfence();
        if (atomicAdd(&bar_cnt, 1u) == (unsigned)(GRID - 1)) {
            bar_cnt = 0;
            __threadfence();
            bar_gen = gen + 1u;
        } else {
            while (bar_gen == gen) __nanosleep(32);
        }
        __threadfence();
    }
    __syncthreads();
}

__device__ __forceinline__ unsigned flip_key(float f) {
    unsigned u = __float_as_uint(f);
    return (u >> 31) ? ~u : (u | 0x80000000u);
}

// ================= THE kernel ================================================
__global__ void __launch_bounds__(TPB, BPSM)
K(const float* __restrict__ x, const float* __restrict__ wr,
  const int* __restrict__ ei, const float* __restrict__ ea,
  const float* __restrict__ W1, const float* __restrict__ W2,
  float* __restrict__ out) {
    __shared__ float sbuf[768];
    const int gtid = blockIdx.x * TPB + threadIdx.x;
    const int t = threadIdx.x;
    const int4*   u4p = reinterpret_cast<const int4*>(ei);
    const int4*   v4p = reinterpret_cast<const int4*>(ei + N_EDGES);
    const float4* a4p = reinterpret_cast<const float4*>(ea);

    // ---- phase 0: zero scratch struct ----
    {
        int4* ps = reinterpret_cast<int4*>(&S);
        const int n16 = (int)(sizeof(Scratch) / 16);
        for (int i = gtid; i < n16; i += GTH) ps[i] = make_int4(0, 0, 0, 0);
    }
    gridbar();

    // ---- phase 1: in-degree (4 edges/iter) + p = x @ w_rank ----
    for (int i = gtid; i < N_EDGES / 4; i += GTH) {
        int4 v4 = __ldg(v4p + i);
        atomicAdd(&S.deg[v4.x], 1);
        atomicAdd(&S.deg[v4.y], 1);
        atomicAdd(&S.deg[v4.z], 1);
        atomicAdd(&S.deg[v4.w], 1);
    }
    {
        float* ws = sbuf;                          // w_rank: 512 floats
        for (int i = t; i < DIM * NH; i += TPB) ws[i] = __ldg(&wr[i]);
        __syncthreads();
        for (int n = gtid; n < N_NODES; n += GTH) {
            const float4* xr = reinterpret_cast<const float4*>(x + (size_t)n * DIM);
            float a0 = 0, a1 = 0, a2 = 0, a3 = 0;
            #pragma unroll 4
            for (int c4 = 0; c4 < DIM / 4; c4++) {
                float4 xv = __ldg(&xr[c4]);
                int b = c4 * 16;
                a0 += xv.x * ws[b+0] + xv.y * ws[b+4] + xv.z * ws[b+8]  + xv.w * ws[b+12];
                a1 += xv.x * ws[b+1] + xv.y * ws[b+5] + xv.z * ws[b+9]  + xv.w * ws[b+13];
                a2 += xv.x * ws[b+2] + xv.y * ws[b+6] + xv.z * ws[b+10] + xv.w * ws[b+14];
                a3 += xv.x * ws[b+3] + xv.y * ws[b+7] + xv.z * ws[b+11] + xv.w * ws[b+15];
            }
            *reinterpret_cast<float4*>(&d_p[n * NH]) = make_float4(a0, a1, a2, a3);
        }
    }
    gridbar();

    // ---- phase 2: q = p * rsqrt(deg) ----
    for (int n = gtid; n < N_NODES; n += GTH) {
        float rs = rsqrtf((float)S.deg[n] + 1.0f);
        float4 p4 = *reinterpret_cast<const float4*>(&d_p[n * NH]);
        *reinterpret_cast<float4*>(&d_q[n * NH]) =
            make_float4(p4.x * rs, p4.y * rs, p4.z * rs, p4.w * rs);
    }
    gridbar();

    // ---- phase 3: acc[v] += q[u]  (4 edges/iter, vector reductions) ----
    for (int i = gtid; i < N_EDGES / 4; i += GTH) {
        int4 u4 = __ldg(u4p + i);
        int4 v4 = __ldg(v4p + i);
        float4 qa = __ldg(reinterpret_cast<const float4*>(&d_q[u4.x * NH]));
        float4 qb = __ldg(reinterpret_cast<const float4*>(&d_q[u4.y * NH]));
        float4 qc = __ldg(reinterpret_cast<const float4*>(&d_q[u4.z * NH]));
        float4 qd = __ldg(reinterpret_cast<const float4*>(&d_q[u4.w * NH]));
        asm volatile("red.global.add.v4.f32 [%0], {%1, %2, %3, %4};"
                     :: "l"(&S.acc[v4.x * NH]), "f"(qa.x), "f"(qa.y), "f"(qa.z), "f"(qa.w) : "memory");
        asm volatile("red.global.add.v4.f32 [%0], {%1, %2, %3, %4};"
                     :: "l"(&S.acc[v4.y * NH]), "f"(qb.x), "f"(qb.y), "f"(qb.z), "f"(qb.w) : "memory");
        asm volatile("red.global.add.v4.f32 [%0], {%1, %2, %3, %4};"
                     :: "l"(&S.acc[v4.z * NH]), "f"(qc.x), "f"(qc.y), "f"(qc.z), "f"(qc.w) : "memory");
        asm volatile("red.global.add.v4.f32 [%0], {%1, %2, %3, %4};"
                     :: "l"(&S.acc[v4.w * NH]), "f"(qd.x), "f"(qd.y), "f"(qd.z), "f"(qd.w) : "memory");
    }
    gridbar();

    // ---- phase 4: scores = p/deg + rsqrt(deg)*acc; histogram top-16 bits ----
    for (int n = gtid; n < N_NODES; n += GTH) {
        float dv  = (float)S.deg[n] + 1.0f;
        float inv = 1.0f / dv;
        float rs  = rsqrtf(dv);
        float4 p4 = *reinterpret_cast<const float4*>(&d_p[n * NH]);
        float4 a4 = *reinterpret_cast<const float4*>(&S.acc[n * NH]);
        float4 s4 = make_float4(p4.x * inv + rs * a4.x, p4.y * inv + rs * a4.y,
                                p4.z * inv + rs * a4.z, p4.w * inv + rs * a4.w);
        *reinterpret_cast<float4*>(&d_scores[n * NH]) = s4;
        atomicAdd(&S.hist[0 * NBINS + (flip_key(s4.x) >> 16)], 1u);
        atomicAdd(&S.hist[1 * NBINS + (flip_key(s4.y) >> 16)], 1u);
        atomicAdd(&S.hist[2 * NBINS + (flip_key(s4.z) >> 16)], 1u);
        atomicAdd(&S.hist[3 * NBINS + (flip_key(s4.w) >> 16)], 1u);
    }
    gridbar();

    // ---- phase 5: per-head coarse scan + threshold + candidate-range prefix ----
    if (blockIdx.x < NH) {
        unsigned* ss = reinterpret_cast<unsigned*>(sbuf);
        int h = blockIdx.x, base = h * NBINS;
        unsigned csum = 0;
        for (int k = 0; k < 256; k++)
            csum += S.hist[base + (NBINS - 1 - (t * 256 + k))];
        ss[t] = csum;
        __syncthreads();
        for (int off = 1; off < 256; off <<= 1) {
            unsigned v = (t >= off) ? ss[t - off] : 0u;
            __syncthreads();
            ss[t] += v;
            __syncthreads();
        }
        unsigned excl = (t > 0) ? ss[t - 1] : 0u;
        if (excl < TOPK) {                         // only chunks intersecting candidates
            bool cross = (excl + csum >= TOPK);
            unsigned run = excl;
            for (int k = 0; k < 256; k++) {
                int bin = NBINS - 1 - (t * 256 + k);
                unsigned hv = S.hist[base + bin];
                d_pref[base + bin] = run;
                if (cross && run < TOPK && run + hv >= TOPK) {
                    d_B[h] = bin; d_cnt[h] = (int)(run + hv);
                }
                run += hv;
            }
        }
    }
    gridbar();

    // ---- phase 6: counting-sort candidates into bin segments ----
    for (int n = gtid; n < N_NODES; n += GTH) {
        float4 s4 = *reinterpret_cast<const float4*>(&d_scores[n * NH]);
        float sv[4] = {s4.x, s4.y, s4.z, s4.w};
        #pragma unroll
        for (int h = 0; h < NH; h++) {
            unsigned key = flip_key(sv[h]);
            int bin = (int)(key >> 16);
            if (bin >= d_B[h]) {
                unsigned slot = atomicAdd(&d_pref[h * NBINS + bin], 1u);
                if (slot < CAP)
                    d_cbuf[h * CAP + slot] =
                        ((unsigned long long)key << 32) | (unsigned)(~(unsigned)n);
            }
        }
    }
    gridbar();

    // ---- phase 7: exact rank = bin base + #greater-in-segment ----
    for (int i = gtid; i < NH * CAP; i += GTH) {
        int h = i / CAP, slot = i % CAP;
        if (slot >= d_cnt[h]) continue;
        unsigned long long key = d_cbuf[h * CAP + slot];
        int bin = (int)(key >> 48);
        unsigned segEnd   = d_pref[h * NBINS + bin];   // post-compact = base+occ
        unsigned occ      = S.hist[h * NBINS + bin];
        unsigned segStart = segEnd - occ;
        int rank = (int)segStart;
        for (unsigned j = segStart; j < segEnd; j++)
            if (d_cbuf[h * CAP + j] > key) rank++;
        if (rank < TOPK) {
            unsigned key32 = (unsigned)(key >> 32);
            int n = (int)(~(unsigned)key);
            float f = __uint_as_float((key32 & 0x80000000u) ? (key32 & 0x7FFFFFFFu)
                                                            : ~key32);
            d_sidx[h * TOPK + rank] = n;
            d_vals[h * TOPK + rank] = f;
            S.locmap[n * NH + h] = (unsigned short)(rank + 1);
        }
    }
    gridbar();

    // ---- phase 8: triples + immediate axpy  y[row] += w * x[node_v] ----
    for (int i = gtid; i < N_EDGES / 4; i += GTH) {
        int4 u4 = __ldg(u4p + i);
        int4 v4 = __ldg(v4p + i);
        int us[4] = {u4.x, u4.y, u4.z, u4.w};
        int vs[4] = {v4.x, v4.y, v4.z, v4.w};
        #pragma unroll
        for (int s = 0; s < 4; s++) {
            ushort4 lu4 = __ldg(reinterpret_cast<const ushort4*>(&S.locmap[us[s] * NH]));
            ushort4 lv4 = __ldg(reinterpret_cast<const ushort4*>(&S.locmap[vs[s] * NH]));
            int lus[4] = {lu4.x, lu4.y, lu4.z, lu4.w};
            int lvs[4] = {lv4.x, lv4.y, lv4.z, lv4.w};
            #pragma unroll
            for (int h = 0; h < NH; h++) {
                int lu = lus[h], lv = lvs[h];
                if (lu == 0 || lv == 0) continue;
                int pu = lu - 1, pv = lv - 1;
                int jju = pu / NK;
                if (jju != pv / NK) continue;
                float w = __ldg(&a4p[i].x + s);     // ea[4*i+s]
                int g   = jju * NH + h;
                int ku  = pu - jju * NK;
                int kv  = pv - jju * NK;
                int row = g * NK + ku;
                int node = d_sidx[h * TOPK + jju * NK + kv];
                if (atomicExch(&S.flag[row], 1) == 0) {
                    int rp = atomicAdd(&S.nrows, 1);
                    d_rows[rp] = row;
                }
                const float4* xr = reinterpret_cast<const float4*>(x + (size_t)node * DIM);
                float* y = &d_msg[(size_t)row * DIM];
                #pragma unroll 4
                for (int c4 = 0; c4 < DIM / 4; c4++) {
                    float4 xv = __ldg(&xr[c4]);
                    asm volatile("red.global.add.v4.f32 [%0], {%1, %2, %3, %4};"
                                 :: "l"(y + c4 * 4),
                                    "f"(w * xv.x), "f"(w * xv.y), "f"(w * xv.z), "f"(w * xv.w)
                                 : "memory");
                }
            }
        }
    }
    gridbar();

    // ---- phase 9: per touched row: msg = y @ W1; pooled += relu(msg)*sig; clear y ----
    {
        float* ys = sbuf;                           // 2 x 128
        int nr = S.nrows;
        int half = t >> 7, tl = t & 127;
        for (int rb = blockIdx.x * 2; rb < nr; rb += GRID * 2) {
            int r = rb + half;
            bool active = (r < nr);
            int row = 0;
            __syncthreads();
            if (active) {
                row = d_rows[r];
                ys[half * DIM + tl] = d_msg[(size_t)row * DIM + tl];
                d_msg[(size_t)row * DIM + tl] = 0.0f;   // restore invariant
            }
            __syncthreads();
            if (active) {
                const float* yrow = &ys[half * DIM];
                float acc = 0.0f;
                #pragma unroll 8
                for (int c = 0; c < DIM; c++) acc += yrow[c] * __ldg(&W1[c * DIM + tl]);
                if (acc > 0.0f) {
                    int g = row / NK, ku = row - g * NK;
                    int h = g & 3, jj = g >> 2;
                    float pv = d_vals[h * TOPK + jj * NK + ku];
                    float sg = 1.0f / (1.0f + expf(-pv));
                    atomicAdd(&S.pooled[jj * DIM + tl], acc * sg);
                }
            }
        }
    }
    gridbar();

    // ---- phase 10: out = log_softmax((pooled/4000) @ W2)  (block 0) ----
    if (blockIdx.x == 0) {
        float* lg   = sbuf;          // 320
        float* red2 = sbuf + 336;    // 16
        for (int i = t; i < NJ * NC; i += TPB) {
            int jj = i / NC, c = i - jj * NC;
            float sacc = 0.0f;
            for (int d = 0; d < DIM; d++)
                sacc += S.pooled[jj * DIM + d] * __ldg(&W2[d * NC + c]);
            lg[i] = sacc * (1.0f / 4000.0f);
        }
        __syncthreads();
        if (t < NJ) {
            float mx = -1e30f;
            for (int c = 0; c < NC; c++) mx = fmaxf(mx, lg[t * NC + c]);
            float se = 0.0f;
            for (int c = 0; c < NC; c++) se += expf(lg[t * NC + c] - mx);
            red2[t * 2] = mx;
            red2[t * 2 + 1] = logf(se);
        }
        __syncthreads();
        for (int i = t; i < NJ * NC; i += TPB) {
            int jj = i / NC;
            out[i] = lg[i] - red2[jj * 2] - red2[jj * 2 + 1];
        }
    }
}

// ---------------- host launcher: ONE node ----------------
extern "C" void kernel_launch(void* const* d_in, const int* in_sizes, int n_in,
                              void* d_out, int out_size) {
    const float* x         = (const float*)d_in[0];
    const float* edge_attr = (const float*)d_in[1];
    const float* w_rank    = (const float*)d_in[2];
    const float* W1        = (const float*)d_in[3];
    const float* W2        = (const float*)d_in[4];
    const int*   ei        = (const int*)d_in[5];
    float*       out       = (float*)d_out;

    K<<<GRID, TPB>>>(x, w_rank, ei, edge_attr, W1, W2, out);
}

// round 7
// speedup vs baseline: 2.1538x; 1.2499x over previous
#include <cuda_runtime.h>
#include <math.h>
#include <stdint.h>

#define N_NODES 100000
#define N_EDGES 1000000
#define DIM     128
#define NH      4
#define NJ      8
#define NK      1000
#define NC      40
#define TOPK    8000            // NJ*NK per head
#define NBINS   65536
#define NCHUNK  256             // 256 chunks x 256 bins
#define CAP     16384
#define NG      32              // NJ*NH
#define NROWS   (NG*NK)         // 32000 msg rows

#define BPSM    6
#define GRID    (148*BPSM)      // 888 blocks, one co-resident wave
#define TPB     256
#define GTH     (GRID*TPB)

// ---------------- zeroed-at-kernel-start scratch (phase 0) --------------------
struct __align__(16) Scratch {
    int            deg[N_NODES];            // in-degree
    unsigned       hist[NH * NBINS];        // per-head 16-bit-key histogram
    int            nrows;
    int            rowctr;
    int            pad0[2];
    unsigned short locmap[N_NODES * NH];    // 0 = absent, else rank+1
    float          acc[N_NODES * NH];       // edge-accumulated sum of q[u]
    int            flag[NROWS];             // msg-row touched flags
    float          pooled[NJ * DIM];
};
__device__ Scratch S;
static_assert(sizeof(Scratch) % 16 == 0, "16B multiple");

// ---------------- other scratch (fully rewritten or self-restoring) -----------
__device__ float               d_p[N_NODES * NH];      // x @ w_rank
__device__ float               d_scores[N_NODES * NH]; // final scores
__device__ unsigned            d_csum[NH * NCHUNK];    // per-chunk bin sums
__device__ unsigned            d_pref[NH * NBINS];     // descending excl prefix
__device__ int                 d_B[NH];                // threshold bin
__device__ int                 d_cnt[NH];              // candidate count
__device__ unsigned long long  d_cbuf[NH * CAP];       // bin-grouped candidate keys
__device__ int                 d_sidx[NH * TOPK];
__device__ float               d_vals[NH * TOPK];
__device__ int                 d_rows[NROWS];          // touched msg rows
__device__ float               d_msg[NROWS * DIM];     // y accumulator; self-cleaning (BSS zero)

// ---------------- grid barrier: GPU-scope acquire/release (no volatile/SYS) ---
__device__ unsigned g_cnt = 0;
__device__ unsigned g_gen = 0;

__device__ __forceinline__ unsigned ld_acq(unsigned* p) {
    unsigned v;
    asm volatile("ld.acquire.gpu.global.u32 %0, [%1];" : "=r"(v) : "l"(p) : "memory");
    return v;
}
__device__ __forceinline__ void st_rel(unsigned* p, unsigned v) {
    asm volatile("st.release.gpu.global.u32 [%0], %1;" :: "l"(p), "r"(v) : "memory");
}

__device__ __forceinline__ void gridbar() {
    __syncthreads();
    if (threadIdx.x == 0) {
        unsigned gen = ld_acq(&g_gen);
        __threadfence();                                 // publish block's writes (gpu scope)
        if (atomicAdd(&g_cnt, 1u) == (unsigned)(GRID - 1)) {
            g_cnt = 0;
            st_rel(&g_gen, gen + 1u);
        } else {
            unsigned ns = 64;
            while (ld_acq(&g_gen) == gen) {
                __nanosleep(ns);
                if (ns < 1024) ns += ns;
            }
        }
    }
    __syncthreads();
}

__device__ __forceinline__ unsigned flip_key(float f) {
    unsigned u = __float_as_uint(f);
    return (u >> 31) ? ~u : (u | 0x80000000u);
}

// ================= THE kernel ================================================
__global__ void __launch_bounds__(TPB, BPSM)
K(const float* __restrict__ x, const float* __restrict__ wr,
  const int* __restrict__ ei, const float* __restrict__ ea,
  const float* __restrict__ W1, const float* __restrict__ W2,
  float* __restrict__ out) {
    __shared__ float sbuf[768];
    __shared__ int   sctl[2];
    const int gtid = blockIdx.x * TPB + threadIdx.x;
    const int t = threadIdx.x;
    const int4* u4p = reinterpret_cast<const int4*>(ei);
    const int4* v4p = reinterpret_cast<const int4*>(ei + N_EDGES);

    // ---- phase 0: zero scratch struct ----
    {
        int4* ps = reinterpret_cast<int4*>(&S);
        const int n16 = (int)(sizeof(Scratch) / 16);
        for (int i = gtid; i < n16; i += GTH) ps[i] = make_int4(0, 0, 0, 0);
    }
    gridbar();

    // ---- phase 1: in-degree (4 edges/iter) + p = x @ w_rank ----
    for (int i = gtid; i < N_EDGES / 4; i += GTH) {
        int4 v4 = __ldg(v4p + i);
        atomicAdd(&S.deg[v4.x], 1);
        atomicAdd(&S.deg[v4.y], 1);
        atomicAdd(&S.deg[v4.z], 1);
        atomicAdd(&S.deg[v4.w], 1);
    }
    {
        float* ws = sbuf;                          // w_rank: 512 floats
        for (int i = t; i < DIM * NH; i += TPB) ws[i] = __ldg(&wr[i]);
        __syncthreads();
        for (int n = gtid; n < N_NODES; n += GTH) {
            const float4* xr = reinterpret_cast<const float4*>(x + (size_t)n * DIM);
            float a0 = 0, a1 = 0, a2 = 0, a3 = 0;
            #pragma unroll 4
            for (int c4 = 0; c4 < DIM / 4; c4++) {
                float4 xv = __ldg(&xr[c4]);
                int b = c4 * 16;
                a0 += xv.x * ws[b+0] + xv.y * ws[b+4] + xv.z * ws[b+8]  + xv.w * ws[b+12];
                a1 += xv.x * ws[b+1] + xv.y * ws[b+5] + xv.z * ws[b+9]  + xv.w * ws[b+13];
                a2 += xv.x * ws[b+2] + xv.y * ws[b+6] + xv.z * ws[b+10] + xv.w * ws[b+14];
                a3 += xv.x * ws[b+3] + xv.y * ws[b+7] + xv.z * ws[b+11] + xv.w * ws[b+15];
            }
            *reinterpret_cast<float4*>(&d_p[n * NH]) = make_float4(a0, a1, a2, a3);
        }
    }
    gridbar();

    // ---- phase 2: acc[v] += rsqrt(deg[u])*p[u]  (q fused on the fly) ----
    for (int i = gtid; i < N_EDGES / 4; i += GTH) {
        int4 u4 = __ldg(u4p + i);
        int4 v4 = __ldg(v4p + i);
        int us[4] = {u4.x, u4.y, u4.z, u4.w};
        int vs[4] = {v4.x, v4.y, v4.z, v4.w};
        #pragma unroll
        for (int s = 0; s < 4; s++) {
            float rs = rsqrtf((float)__ldg(&S.deg[us[s]]) + 1.0f);
            float4 p4 = __ldg(reinterpret_cast<const float4*>(&d_p[us[s] * NH]));
            asm volatile("red.global.add.v4.f32 [%0], {%1, %2, %3, %4};"
                         :: "l"(&S.acc[vs[s] * NH]),
                            "f"(rs * p4.x), "f"(rs * p4.y), "f"(rs * p4.z), "f"(rs * p4.w)
                         : "memory");
        }
    }
    gridbar();

    // ---- phase 3: scores = p/deg + rsqrt(deg)*acc; histogram top-16 bits ----
    for (int n = gtid; n < N_NODES; n += GTH) {
        float dv  = (float)S.deg[n] + 1.0f;
        float inv = 1.0f / dv;
        float rs  = rsqrtf(dv);
        float4 p4 = *reinterpret_cast<const float4*>(&d_p[n * NH]);
        float4 a4 = *reinterpret_cast<const float4*>(&S.acc[n * NH]);
        float4 s4 = make_float4(p4.x * inv + rs * a4.x, p4.y * inv + rs * a4.y,
                                p4.z * inv + rs * a4.z, p4.w * inv + rs * a4.w);
        *reinterpret_cast<float4*>(&d_scores[n * NH]) = s4;
        atomicAdd(&S.hist[0 * NBINS + (flip_key(s4.x) >> 16)], 1u);
        atomicAdd(&S.hist[1 * NBINS + (flip_key(s4.y) >> 16)], 1u);
        atomicAdd(&S.hist[2 * NBINS + (flip_key(s4.z) >> 16)], 1u);
        atomicAdd(&S.hist[3 * NBINS + (flip_key(s4.w) >> 16)], 1u);
    }
    gridbar();

    // ---- phase 4: chunk sums (1024 parallel coalesced jobs) ----
    {
        unsigned* sh = reinterpret_cast<unsigned*>(sbuf);
        for (int j = blockIdx.x; j < NH * NCHUNK; j += GRID) {
            int h = j >> 8, c = j & 255;
            // chunk c covers descending positions [c*256, c*256+255] -> bins 65535-pos
            unsigned hv = S.hist[h * NBINS + (NBINS - 1 - (c * 256 + t))];
            sh[t] = hv;
            __syncthreads();
            for (int off = 128; off; off >>= 1) {
                if (t < off) sh[t] += sh[t + off];
                __syncthreads();
            }
            if (t == 0) d_csum[h * NCHUNK + c] = sh[0];
            __syncthreads();
        }
    }
    gridbar();

    // ---- phase 5: per-chunk prefix + per-bin prefix + threshold (1024 jobs) ----
    {
        unsigned* sh = reinterpret_cast<unsigned*>(sbuf);          // 256: chunk scan
        unsigned* sb = reinterpret_cast<unsigned*>(sbuf) + 256;    // 256: bin scan
        for (int j = blockIdx.x; j < NH * NCHUNK; j += GRID) {
            int h = j >> 8, c = j & 255;
            // scan chunk sums of this head (redundant per job, trivial)
            sh[t] = d_csum[h * NCHUNK + t];
            __syncthreads();
            for (int off = 1; off < 256; off <<= 1) {
                unsigned v = (t >= off) ? sh[t - off] : 0u;
                __syncthreads();
                sh[t] += v;
                __syncthreads();
            }
            unsigned base = (c > 0) ? sh[c - 1] : 0u;
            // intra-chunk bin scan
            int bin = NBINS - 1 - (c * 256 + t);
            unsigned hv = S.hist[h * NBINS + bin];
            sb[t] = hv;
            __syncthreads();
            for (int off = 1; off < 256; off <<= 1) {
                unsigned v = (t >= off) ? sb[t - off] : 0u;
                __syncthreads();
                sb[t] += v;
                __syncthreads();
            }
            unsigned excl = base + sb[t] - hv;
            d_pref[h * NBINS + bin] = excl;
            if (excl < TOPK && excl + hv >= TOPK) {     // unique crossing bin
                d_B[h]   = bin;
                d_cnt[h] = (int)(excl + hv);
            }
            __syncthreads();
        }
    }
    gridbar();

    // ---- phase 6: counting-sort candidates into bin segments ----
    for (int n = gtid; n < N_NODES; n += GTH) {
        float4 s4 = *reinterpret_cast<const float4*>(&d_scores[n * NH]);
        float sv[4] = {s4.x, s4.y, s4.z, s4.w};
        #pragma unroll
        for (int h = 0; h < NH; h++) {
            unsigned key = flip_key(sv[h]);
            int bin = (int)(key >> 16);
            if (bin >= d_B[h]) {
                unsigned slot = atomicAdd(&d_pref[h * NBINS + bin], 1u);
                if (slot < CAP)
                    d_cbuf[h * CAP + slot] =
                        ((unsigned long long)key << 32) | (unsigned)(~(unsigned)n);
            }
        }
    }
    gridbar();

    // ---- phase 7: exact rank = bin base + #greater-in-segment ----
    for (int i = gtid; i < NH * CAP; i += GTH) {
        int h = i / CAP, slot = i % CAP;
        if (slot >= d_cnt[h]) continue;
        unsigned long long key = d_cbuf[h * CAP + slot];
        int bin = (int)(key >> 48);
        unsigned segEnd   = d_pref[h * NBINS + bin];   // post-compact = base+occ
        unsigned occ      = S.hist[h * NBINS + bin];
        unsigned segStart = segEnd - occ;
        int rank = (int)segStart;
        for (unsigned j = segStart; j < segEnd; j++)
            if (d_cbuf[h * CAP + j] > key) rank++;
        if (rank < TOPK) {
            unsigned key32 = (unsigned)(key >> 32);
            int n = (int)(~(unsigned)key);
            float f = __uint_as_float((key32 & 0x80000000u) ? (key32 & 0x7FFFFFFFu)
                                                            : ~key32);
            d_sidx[h * TOPK + rank] = n;
            d_vals[h * TOPK + rank] = f;
            S.locmap[n * NH + h] = (unsigned short)(rank + 1);
        }
    }
    gridbar();

    // ---- phase 8: triples + immediate axpy  y[row] += w * x[node_v] ----
    for (int i = gtid; i < N_EDGES / 4; i += GTH) {
        int4 u4 = __ldg(u4p + i);
        int4 v4 = __ldg(v4p + i);
        int us[4] = {u4.x, u4.y, u4.z, u4.w};
        int vs[4] = {v4.x, v4.y, v4.z, v4.w};
        #pragma unroll
        for (int s = 0; s < 4; s++) {
            ushort4 lu4 = __ldg(reinterpret_cast<const ushort4*>(&S.locmap[us[s] * NH]));
            ushort4 lv4 = __ldg(reinterpret_cast<const ushort4*>(&S.locmap[vs[s] * NH]));
            int lus[4] = {lu4.x, lu4.y, lu4.z, lu4.w};
            int lvs[4] = {lv4.x, lv4.y, lv4.z, lv4.w};
            #pragma unroll
            for (int h = 0; h < NH; h++) {
                int lu = lus[h], lv = lvs[h];
                if (lu == 0 || lv == 0) continue;
                int pu = lu - 1, pv = lv - 1;
                int jju = pu / NK;
                if (jju != pv / NK) continue;
                float w = __ldg(&ea[4 * i + s]);
                int g   = jju * NH + h;
                int ku  = pu - jju * NK;
                int kv  = pv - jju * NK;
                int row = g * NK + ku;
                int node = d_sidx[h * TOPK + jju * NK + kv];
                if (atomicExch(&S.flag[row], 1) == 0) {
                    int rp = atomicAdd(&S.nrows, 1);
                    d_rows[rp] = row;
                }
                const float4* xr = reinterpret_cast<const float4*>(x + (size_t)node * DIM);
                float* y = &d_msg[(size_t)row * DIM];
                #pragma unroll 4
                for (int c4 = 0; c4 < DIM / 4; c4++) {
                    float4 xv = __ldg(&xr[c4]);
                    asm volatile("red.global.add.v4.f32 [%0], {%1, %2, %3, %4};"
                                 :: "l"(y + c4 * 4),
                                    "f"(w * xv.x), "f"(w * xv.y), "f"(w * xv.z), "f"(w * xv.w)
                                 : "memory");
                }
            }
        }
    }
    gridbar();

    // ---- phase 9: dynamic rows: msg = y @ W1; pooled += relu*sig; clear y ----
    {
        float* ys = sbuf;                           // 2 x 128
        int nr = S.nrows;
        int half = t >> 7, tl = t & 127;
        for (;;) {
            __syncthreads();
            if (t == 0) sctl[0] = atomicAdd(&S.rowctr, 2);
            __syncthreads();
            int rb = sctl[0];
            if (rb >= nr) break;
            int r = rb + half;
            bool active = (r < nr);
            int row = 0;
            if (active) {
                row = d_rows[r];
                ys[half * DIM + tl] = d_msg[(size_t)row * DIM + tl];
                d_msg[(size_t)row * DIM + tl] = 0.0f;   // restore invariant
            }
            __syncthreads();
            if (active) {
                const float* yrow = &ys[half * DIM];
                float acc = 0.0f;
                #pragma unroll 8
                for (int c = 0; c < DIM; c++) acc += yrow[c] * __ldg(&W1[c * DIM + tl]);
                if (acc > 0.0f) {
                    int g = row / NK, ku = row - g * NK;
                    int h = g & 3, jj = g >> 2;
                    float pv = d_vals[h * TOPK + jj * NK + ku];
                    float sg = 1.0f / (1.0f + expf(-pv));
                    atomicAdd(&S.pooled[jj * DIM + tl], acc * sg);
                }
            }
        }
    }
    gridbar();

    // ---- phase 10: out = log_softmax((pooled/4000) @ W2)  (block 0) ----
    if (blockIdx.x == 0) {
        float* lg   = sbuf;          // 320
        float* red2 = sbuf + 336;    // 16
        for (int i = t; i < NJ * NC; i += TPB) {
            int jj = i / NC, c = i - jj * NC;
            float sacc = 0.0f;
            for (int d = 0; d < DIM; d++)
                sacc += S.pooled[jj * DIM + d] * __ldg(&W2[d * NC + c]);
            lg[i] = sacc * (1.0f / 4000.0f);
        }
        __syncthreads();
        if (t < NJ) {
            float mx = -1e30f;
            for (int c = 0; c < NC; c++) mx = fmaxf(mx, lg[t * NC + c]);
            float se = 0.0f;
            for (int c = 0; c < NC; c++) se += expf(lg[t * NC + c] - mx);
            red2[t * 2] = mx;
            red2[t * 2 + 1] = logf(se);
        }
        __syncthreads();
        for (int i = t; i < NJ * NC; i += TPB) {
            int jj = i / NC;
            out[i] = lg[i] - red2[jj * 2] - red2[jj * 2 + 1];
        }
    }
}

// ---------------- host launcher: ONE node ----------------
extern "C" void kernel_launch(void* const* d_in, const int* in_sizes, int n_in,
                              void* d_out, int out_size) {
    const float* x         = (const float*)d_in[0];
    const float* edge_attr = (const float*)d_in[1];
    const float* w_rank    = (const float*)d_in[2];
    const float* W1        = (const float*)d_in[3];
    const float* W2        = (const float*)d_in[4];
    const int*   ei        = (const int*)d_in[5];
    float*       out       = (float*)d_out;

    K<<<GRID, TPB>>>(x, w_rank, ei, edge_attr, W1, W2, out);
}

// round 8
// speedup vs baseline: 2.2496x; 1.0445x over previous
#include <cuda_runtime.h>
#include <math.h>
#include <stdint.h>

#define N_NODES 100000
#define N_EDGES 1000000
#define DIM     128
#define NH      4
#define NJ      8
#define NK      1000
#define NC      40
#define TOPK    8000            // NJ*NK per head
#define NBINS   65536
#define NCHUNK  256             // 256 chunks x 256 bins
#define CAP     16384
#define NG      32              // NJ*NH
#define NROWS   (NG*NK)         // 32000 msg rows

#define BPSM    6
#define GRID    (148*BPSM)      // 888 blocks, one co-resident wave
#define TPB     256
#define GTH     (GRID*TPB)

// ---------------- scratch, split by zeroing phase -----------------------------
struct __align__(16) SA_t {       // zeroed in phase 0 (tiny)
    int deg[N_NODES];
    int nrows;
    int rowctr;
    int pad[2];
};
struct __align__(16) SB_t {       // zeroed during phase 1
    unsigned hist[NH * NBINS];
    float    acc[N_NODES * NH];
};
struct __align__(16) SC_t {       // zeroed during phase 2
    unsigned short locmap[N_NODES * NH];   // 0 = absent, else rank+1
    int            flag[NROWS];
    float          pooled[NJ * DIM];
};
__device__ SA_t SA;
__device__ SB_t SB;
__device__ SC_t SC;
static_assert(sizeof(SA_t) % 16 == 0, "");
static_assert(sizeof(SB_t) % 16 == 0, "");
static_assert(sizeof(SC_t) % 16 == 0, "");

// ---------------- other scratch (fully rewritten or self-restoring) -----------
__device__ float               d_p[N_NODES * NH];      // x @ w_rank
__device__ float               d_scores[N_NODES * NH]; // final scores
__device__ unsigned            d_csum[NH * NCHUNK];    // per-chunk bin sums
__device__ unsigned            d_pref[NH * NBINS];     // descending excl prefix
__device__ int                 d_B[NH];                // threshold bin
__device__ int                 d_cnt[NH];              // candidate count
__device__ unsigned long long  d_cbuf[NH * CAP];       // bin-grouped candidate keys
__device__ int                 d_sidx[NH * TOPK];
__device__ float               d_vals[NH * TOPK];
__device__ int                 d_rows[NROWS];          // touched msg rows
__device__ float               d_msg[NROWS * DIM];     // y accumulator; self-cleaning (BSS zero)

// ---------------- grid barrier: GPU-scope acquire/release ---------------------
__device__ unsigned g_cnt = 0;
__device__ unsigned g_gen = 0;

__device__ __forceinline__ unsigned ld_acq(unsigned* p) {
    unsigned v;
    asm volatile("ld.acquire.gpu.global.u32 %0, [%1];" : "=r"(v) : "l"(p) : "memory");
    return v;
}
__device__ __forceinline__ void st_rel(unsigned* p, unsigned v) {
    asm volatile("st.release.gpu.global.u32 [%0], %1;" :: "l"(p), "r"(v) : "memory");
}

__device__ __forceinline__ void gridbar() {
    __syncthreads();
    if (threadIdx.x == 0) {
        unsigned gen = ld_acq(&g_gen);
        __threadfence();
        if (atomicAdd(&g_cnt, 1u) == (unsigned)(GRID - 1)) {
            g_cnt = 0;
            st_rel(&g_gen, gen + 1u);
        } else {
            unsigned ns = 16;
            while (ld_acq(&g_gen) == gen) {
                __nanosleep(ns);
                if (ns < 256) ns += ns;
            }
        }
    }
    __syncthreads();
}

__device__ __forceinline__ unsigned flip_key(float f) {
    unsigned u = __float_as_uint(f);
    return (u >> 31) ? ~u : (u | 0x80000000u);
}

// ================= THE kernel ================================================
__global__ void __launch_bounds__(TPB, BPSM)
K(const float* __restrict__ x, const float* __restrict__ wr,
  const int* __restrict__ ei, const float* __restrict__ ea,
  const float* __restrict__ W1, const float* __restrict__ W2,
  float* __restrict__ out) {
    __shared__ float sbuf[768];
    __shared__ int   sctl[2];
    const int gtid = blockIdx.x * TPB + threadIdx.x;
    const int t = threadIdx.x;
    const int4* u4p = reinterpret_cast<const int4*>(ei);
    const int4* v4p = reinterpret_cast<const int4*>(ei + N_EDGES);

    // ---- phase 0: zero SA only (deg + counters) ----
    {
        int4* ps = reinterpret_cast<int4*>(&SA);
        const int n16 = (int)(sizeof(SA_t) / 16);
        for (int i = gtid; i < n16; i += GTH) ps[i] = make_int4(0, 0, 0, 0);
    }
    gridbar();

    // ---- phase 1: zero SB + in-degree + p = x @ w_rank ----
    {
        int4* ps = reinterpret_cast<int4*>(&SB);
        const int n16 = (int)(sizeof(SB_t) / 16);
        for (int i = gtid; i < n16; i += GTH) ps[i] = make_int4(0, 0, 0, 0);
    }
    for (int i = gtid; i < N_EDGES / 4; i += GTH) {
        int4 v4 = __ldg(v4p + i);
        atomicAdd(&SA.deg[v4.x], 1);
        atomicAdd(&SA.deg[v4.y], 1);
        atomicAdd(&SA.deg[v4.z], 1);
        atomicAdd(&SA.deg[v4.w], 1);
    }
    {
        float* ws = sbuf;                          // w_rank: 512 floats
        for (int i = t; i < DIM * NH; i += TPB) ws[i] = __ldg(&wr[i]);
        __syncthreads();
        for (int n = gtid; n < N_NODES; n += GTH) {
            const float4* xr = reinterpret_cast<const float4*>(x + (size_t)n * DIM);
            float a0 = 0, a1 = 0, a2 = 0, a3 = 0;
            #pragma unroll 4
            for (int c4 = 0; c4 < DIM / 4; c4++) {
                float4 xv = __ldg(&xr[c4]);
                int b = c4 * 16;
                a0 += xv.x * ws[b+0] + xv.y * ws[b+4] + xv.z * ws[b+8]  + xv.w * ws[b+12];
                a1 += xv.x * ws[b+1] + xv.y * ws[b+5] + xv.z * ws[b+9]  + xv.w * ws[b+13];
                a2 += xv.x * ws[b+2] + xv.y * ws[b+6] + xv.z * ws[b+10] + xv.w * ws[b+14];
                a3 += xv.x * ws[b+3] + xv.y * ws[b+7] + xv.z * ws[b+11] + xv.w * ws[b+15];
            }
            *reinterpret_cast<float4*>(&d_p[n * NH]) = make_float4(a0, a1, a2, a3);
        }
    }
    gridbar();

    // ---- phase 2: zero SC + acc[v] += rsqrt(deg[u])*p[u] ----
    {
        int4* ps = reinterpret_cast<int4*>(&SC);
        const int n16 = (int)(sizeof(SC_t) / 16);
        for (int i = gtid; i < n16; i += GTH) ps[i] = make_int4(0, 0, 0, 0);
    }
    for (int i = gtid; i < N_EDGES / 4; i += GTH) {
        int4 u4 = __ldg(u4p + i);
        int4 v4 = __ldg(v4p + i);
        int us[4] = {u4.x, u4.y, u4.z, u4.w};
        int vs[4] = {v4.x, v4.y, v4.z, v4.w};
        // batch all independent gathers first (max MLP)
        int dg[4]; float4 pp[4];
        #pragma unroll
        for (int s = 0; s < 4; s++) dg[s] = __ldg(&SA.deg[us[s]]);
        #pragma unroll
        for (int s = 0; s < 4; s++)
            pp[s] = __ldg(reinterpret_cast<const float4*>(&d_p[us[s] * NH]));
        #pragma unroll
        for (int s = 0; s < 4; s++) {
            float rs = rsqrtf((float)dg[s] + 1.0f);
            asm volatile("red.global.add.v4.f32 [%0], {%1, %2, %3, %4};"
                         :: "l"(&SB.acc[vs[s] * NH]),
                            "f"(rs * pp[s].x), "f"(rs * pp[s].y),
                            "f"(rs * pp[s].z), "f"(rs * pp[s].w)
                         : "memory");
        }
    }
    gridbar();

    // ---- phase 3: scores = p/deg + rsqrt(deg)*acc; histogram top-16 bits ----
    for (int n = gtid; n < N_NODES; n += GTH) {
        float dv  = (float)SA.deg[n] + 1.0f;
        float inv = 1.0f / dv;
        float rs  = rsqrtf(dv);
        float4 p4 = *reinterpret_cast<const float4*>(&d_p[n * NH]);
        float4 a4 = *reinterpret_cast<const float4*>(&SB.acc[n * NH]);
        float4 s4 = make_float4(p4.x * inv + rs * a4.x, p4.y * inv + rs * a4.y,
                                p4.z * inv + rs * a4.z, p4.w * inv + rs * a4.w);
        *reinterpret_cast<float4*>(&d_scores[n * NH]) = s4;
        atomicAdd(&SB.hist[0 * NBINS + (flip_key(s4.x) >> 16)], 1u);
        atomicAdd(&SB.hist[1 * NBINS + (flip_key(s4.y) >> 16)], 1u);
        atomicAdd(&SB.hist[2 * NBINS + (flip_key(s4.z) >> 16)], 1u);
        atomicAdd(&SB.hist[3 * NBINS + (flip_key(s4.w) >> 16)], 1u);
    }
    gridbar();

    // ---- phase 4: chunk sums (1024 parallel coalesced jobs) ----
    {
        unsigned* sh = reinterpret_cast<unsigned*>(sbuf);
        for (int j = blockIdx.x; j < NH * NCHUNK; j += GRID) {
            int h = j >> 8, c = j & 255;
            unsigned hv = SB.hist[h * NBINS + (NBINS - 1 - (c * 256 + t))];
            sh[t] = hv;
            __syncthreads();
            for (int off = 128; off; off >>= 1) {
                if (t < off) sh[t] += sh[t + off];
                __syncthreads();
            }
            if (t == 0) d_csum[h * NCHUNK + c] = sh[0];
            __syncthreads();
        }
    }
    gridbar();

    // ---- phase 5: per-chunk prefix + per-bin prefix + threshold (1024 jobs) ----
    {
        unsigned* sh = reinterpret_cast<unsigned*>(sbuf);
        unsigned* sb = reinterpret_cast<unsigned*>(sbuf) + 256;
        for (int j = blockIdx.x; j < NH * NCHUNK; j += GRID) {
            int h = j >> 8, c = j & 255;
            sh[t] = d_csum[h * NCHUNK + t];
            __syncthreads();
            for (int off = 1; off < 256; off <<= 1) {
                unsigned v = (t >= off) ? sh[t - off] : 0u;
                __syncthreads();
                sh[t] += v;
                __syncthreads();
            }
            unsigned base = (c > 0) ? sh[c - 1] : 0u;
            int bin = NBINS - 1 - (c * 256 + t);
            unsigned hv = SB.hist[h * NBINS + bin];
            sb[t] = hv;
            __syncthreads();
            for (int off = 1; off < 256; off <<= 1) {
                unsigned v = (t >= off) ? sb[t - off] : 0u;
                __syncthreads();
                sb[t] += v;
                __syncthreads();
            }
            unsigned excl = base + sb[t] - hv;
            d_pref[h * NBINS + bin] = excl;
            if (excl < TOPK && excl + hv >= TOPK) {
                d_B[h]   = bin;
                d_cnt[h] = (int)(excl + hv);
            }
            __syncthreads();
        }
    }
    gridbar();

    // ---- phase 6: counting-sort candidates into bin segments ----
    {
        int B0 = d_B[0], B1 = d_B[1], B2 = d_B[2], B3 = d_B[3];
        int Bs[4] = {B0, B1, B2, B3};
        for (int n = gtid; n < N_NODES; n += GTH) {
            float4 s4 = *reinterpret_cast<const float4*>(&d_scores[n * NH]);
            float sv[4] = {s4.x, s4.y, s4.z, s4.w};
            #pragma unroll
            for (int h = 0; h < NH; h++) {
                unsigned key = flip_key(sv[h]);
                int bin = (int)(key >> 16);
                if (bin >= Bs[h]) {
                    unsigned slot = atomicAdd(&d_pref[h * NBINS + bin], 1u);
                    if (slot < CAP)
                        d_cbuf[h * CAP + slot] =
                            ((unsigned long long)key << 32) | (unsigned)(~(unsigned)n);
                }
            }
        }
    }
    gridbar();

    // ---- phase 7: exact rank = bin base + #greater-in-segment ----
    for (int i = gtid; i < NH * CAP; i += GTH) {
        int h = i / CAP, slot = i % CAP;
        if (slot >= d_cnt[h]) continue;
        unsigned long long key = d_cbuf[h * CAP + slot];
        int bin = (int)(key >> 48);
        unsigned segEnd   = d_pref[h * NBINS + bin];   // post-compact = base+occ
        unsigned occ      = SB.hist[h * NBINS + bin];
        unsigned segStart = segEnd - occ;
        int rank = (int)segStart;
        for (unsigned j = segStart; j < segEnd; j++)
            if (d_cbuf[h * CAP + j] > key) rank++;
        if (rank < TOPK) {
            unsigned key32 = (unsigned)(key >> 32);
            int n = (int)(~(unsigned)key);
            float f = __uint_as_float((key32 & 0x80000000u) ? (key32 & 0x7FFFFFFFu)
                                                            : ~key32);
            d_sidx[h * TOPK + rank] = n;
            d_vals[h * TOPK + rank] = f;
            SC.locmap[n * NH + h] = (unsigned short)(rank + 1);
        }
    }
    gridbar();

    // ---- phase 8: triples + immediate axpy  y[row] += w * x[node_v] ----
    for (int i = gtid; i < N_EDGES / 4; i += GTH) {
        int4 u4 = __ldg(u4p + i);
        int4 v4 = __ldg(v4p + i);
        int us[4] = {u4.x, u4.y, u4.z, u4.w};
        int vs[4] = {v4.x, v4.y, v4.z, v4.w};
        // batch all 8 locmap gathers (8B each) before processing
        unsigned long long LU[4], LV[4];
        #pragma unroll
        for (int s = 0; s < 4; s++)
            LU[s] = __ldg(reinterpret_cast<const unsigned long long*>(&SC.locmap[us[s] * NH]));
        #pragma unroll
        for (int s = 0; s < 4; s++)
            LV[s] = __ldg(reinterpret_cast<const unsigned long long*>(&SC.locmap[vs[s] * NH]));
        #pragma unroll
        for (int s = 0; s < 4; s++) {
            if (LU[s] == 0ull || LV[s] == 0ull) continue;   // fast reject ~92%
            #pragma unroll
            for (int h = 0; h < NH; h++) {
                int lu = (int)((LU[s] >> (16 * h)) & 0xFFFFu);
                int lv = (int)((LV[s] >> (16 * h)) & 0xFFFFu);
                if (lu == 0 || lv == 0) continue;
                int pu = lu - 1, pv = lv - 1;
                int jju = pu / NK;
                if (jju != pv / NK) continue;
                float w = __ldg(&ea[4 * i + s]);
                int g   = jju * NH + h;
                int ku  = pu - jju * NK;
                int kv  = pv - jju * NK;
                int row = g * NK + ku;
                int node = d_sidx[h * TOPK + jju * NK + kv];
                if (atomicExch(&SC.flag[row], 1) == 0) {
                    int rp = atomicAdd(&SA.nrows, 1);
                    d_rows[rp] = row;
                }
                const float4* xr = reinterpret_cast<const float4*>(x + (size_t)node * DIM);
                float* y = &d_msg[(size_t)row * DIM];
                #pragma unroll 4
                for (int c4 = 0; c4 < DIM / 4; c4++) {
                    float4 xv = __ldg(&xr[c4]);
                    asm volatile("red.global.add.v4.f32 [%0], {%1, %2, %3, %4};"
                                 :: "l"(y + c4 * 4),
                                    "f"(w * xv.x), "f"(w * xv.y), "f"(w * xv.z), "f"(w * xv.w)
                                 : "memory");
                }
            }
        }
    }
    gridbar();

    // ---- phase 9: dynamic rows: msg = y @ W1; pooled += relu*sig; clear y ----
    {
        float* ys = sbuf;                           // 2 x 128
        int nr = SA.nrows;
        int half = t >> 7, tl = t & 127;
        for (;;) {
            __syncthreads();
            if (t == 0) sctl[0] = atomicAdd(&SA.rowctr, 2);
            __syncthreads();
            int rb = sctl[0];
            if (rb >= nr) break;
            int r = rb + half;
            bool active = (r < nr);
            int row = 0;
            if (active) {
                row = d_rows[r];
                ys[half * DIM + tl] = d_msg[(size_t)row * DIM + tl];
                d_msg[(size_t)row * DIM + tl] = 0.0f;   // restore invariant
            }
            __syncthreads();
            if (active) {
                const float* yrow = &ys[half * DIM];
                float acc = 0.0f;
                #pragma unroll 8
                for (int c = 0; c < DIM; c++) acc += yrow[c] * __ldg(&W1[c * DIM + tl]);
                if (acc > 0.0f) {
                    int g = row / NK, ku = row - g * NK;
                    int h = g & 3, jj = g >> 2;
                    float pv = d_vals[h * TOPK + jj * NK + ku];
                    float sg = 1.0f / (1.0f + __expf(-pv));
                    atomicAdd(&SC.pooled[jj * DIM + tl], acc * sg);
                }
            }
        }
    }
    gridbar();

    // ---- phase 10: out = log_softmax((pooled/4000) @ W2)  (block 0) ----
    if (blockIdx.x == 0) {
        float* lg   = sbuf;          // 320
        float* red2 = sbuf + 336;    // 16
        for (int i = t; i < NJ * NC; i += TPB) {
            int jj = i / NC, c = i - jj * NC;
            float sacc = 0.0f;
            for (int d = 0; d < DIM; d++)
                sacc += SC.pooled[jj * DIM + d] * __ldg(&W2[d * NC + c]);
            lg[i] = sacc * (1.0f / 4000.0f);
        }
        __syncthreads();
        if (t < NJ) {
            float mx = -1e30f;
            for (int c = 0; c < NC; c++) mx = fmaxf(mx, lg[t * NC + c]);
            float se = 0.0f;
            for (int c = 0; c < NC; c++) se += __expf(lg[t * NC + c] - mx);
            red2[t * 2] = mx;
            red2[t * 2 + 1] = __logf(se);
        }
        __syncthreads();
        for (int i = t; i < NJ * NC; i += TPB) {
            int jj = i / NC;
            out[i] = lg[i] - red2[jj * 2] - red2[jj * 2 + 1];
        }
    }
}

// ---------------- host launcher: ONE node ----------------
extern "C" void kernel_launch(void* const* d_in, const int* in_sizes, int n_in,
                              void* d_out, int out_size) {
    const float* x         = (const float*)d_in[0];
    const float* edge_attr = (const float*)d_in[1];
    const float* w_rank    = (const float*)d_in[2];
    const float* W1        = (const float*)d_in[3];
    const float* W2        = (const float*)d_in[4];
    const int*   ei        = (const int*)d_in[5];
    float*       out       = (float*)d_out;

    K<<<GRID, TPB>>>(x, w_rank, ei, edge_attr, W1, W2, out);
}